// round 3
// baseline (speedup 1.0000x reference)
#include <cuda_runtime.h>
#include <math_constants.h>
#include <cstdint>

// Problem constants
#define B_SZ   2
#define L_SEQ  2048
#define D_MOD  1024
#define NH     16
#define HD     64
#define M_ROWS (B_SZ * L_SEQ)   // 4096

// Scratch (allocation-free rule: __device__ globals)
__device__ float g_q[M_ROWS * D_MOD];
__device__ float g_k[M_ROWS * D_MOD];
__device__ float g_v[M_ROWS * D_MOD];
__device__ float g_attn[M_ROWS * D_MOD];

// ---------------------------------------------------------------------------
// tf32 helpers
// ---------------------------------------------------------------------------
__device__ __forceinline__ float tf32r(float x) {
    uint32_t u;
    asm("cvt.rna.tf32.f32 %0, %1;" : "=r"(u) : "f"(x));
    return __uint_as_float(u);
}

__device__ __forceinline__ void mma_tf32(float c[4],
                                         float a0, float a1, float a2, float a3,
                                         float b0, float b1)
{
    asm volatile(
        "mma.sync.aligned.m16n8k8.row.col.f32.tf32.tf32.f32 "
        "{%0,%1,%2,%3},{%4,%5,%6,%7},{%8,%9},{%0,%1,%2,%3};"
        : "+f"(c[0]), "+f"(c[1]), "+f"(c[2]), "+f"(c[3])
        : "r"(__float_as_uint(a0)), "r"(__float_as_uint(a1)),
          "r"(__float_as_uint(a2)), "r"(__float_as_uint(a3)),
          "r"(__float_as_uint(b0)), "r"(__float_as_uint(b1)));
}

// ---------------------------------------------------------------------------
// tf32 tensor-core GEMM, ping-pong double buffered smem.
// C[M,Nc] = alpha * A[M,K] @ W[K,Nc]  (row-major). BM=BN=128, BK=16, 8 warps.
// ---------------------------------------------------------------------------
struct GemmTriple {
    const float* A[3];
    const float* W[3];
    float*       C[3];
    float        alpha[3];
};

template <int NZ>
__global__ void __launch_bounds__(256, 2)
mma_gemm(GemmTriple args, int M, int Nc, int K)
{
    constexpr int SA = 136;   // 136%32==8 -> conflict-free fragment reads
    __shared__ float As[2][16 * SA];  // [k][m]
    __shared__ float Ws[2][16 * SA];  // [k][n]

    const int z = (NZ > 1) ? blockIdx.z : 0;
    const float* __restrict__ A = args.A[z];
    const float* __restrict__ W = args.W[z];
    float* __restrict__ C = args.C[z];
    const float alpha = args.alpha[z];

    const int tid  = threadIdx.x;
    const int lane = tid & 31;
    const int w    = tid >> 5;
    const int g    = lane >> 2;
    const int tig  = lane & 3;
    const int mbase = (w >> 2) * 64;
    const int nbase = (w & 3) * 32;
    const int bx = blockIdx.x, by = blockIdx.y;

    const int ar  = tid & 63;
    const int acq = tid >> 6;
    const int wr  = tid >> 5;
    const int wc  = (tid & 31) * 4;

    const float* Ap = A + (size_t)(by * 128 + ar) * K + acq * 4;
    const float* Wp = W + (size_t)wr * Nc + bx * 128 + wc;

    float acc[4][4][4];
#pragma unroll
    for (int mt = 0; mt < 4; ++mt)
#pragma unroll
        for (int nt = 0; nt < 4; ++nt)
#pragma unroll
            for (int i = 0; i < 4; ++i) acc[mt][nt][i] = 0.f;

    float4 a0r, a1r, w0r, w1r;
    auto ldtile = [&](int k0) {
        a0r = *(const float4*)(Ap + k0);
        a1r = *(const float4*)(Ap + (size_t)64 * K + k0);
        w0r = *(const float4*)(Wp + (size_t)k0 * Nc);
        w1r = *(const float4*)(Wp + (size_t)(k0 + 8) * Nc);
    };
    auto sttile = [&](int buf) {
        float* Ab = As[buf];
        float* Wb = Ws[buf];
        Ab[(acq * 4 + 0) * SA + ar] = tf32r(a0r.x);
        Ab[(acq * 4 + 1) * SA + ar] = tf32r(a0r.y);
        Ab[(acq * 4 + 2) * SA + ar] = tf32r(a0r.z);
        Ab[(acq * 4 + 3) * SA + ar] = tf32r(a0r.w);
        Ab[(acq * 4 + 0) * SA + ar + 64] = tf32r(a1r.x);
        Ab[(acq * 4 + 1) * SA + ar + 64] = tf32r(a1r.y);
        Ab[(acq * 4 + 2) * SA + ar + 64] = tf32r(a1r.z);
        Ab[(acq * 4 + 3) * SA + ar + 64] = tf32r(a1r.w);
        Wb[wr * SA + wc + 0] = tf32r(w0r.x);
        Wb[wr * SA + wc + 1] = tf32r(w0r.y);
        Wb[wr * SA + wc + 2] = tf32r(w0r.z);
        Wb[wr * SA + wc + 3] = tf32r(w0r.w);
        Wb[(wr + 8) * SA + wc + 0] = tf32r(w1r.x);
        Wb[(wr + 8) * SA + wc + 1] = tf32r(w1r.y);
        Wb[(wr + 8) * SA + wc + 2] = tf32r(w1r.z);
        Wb[(wr + 8) * SA + wc + 3] = tf32r(w1r.w);
    };

    ldtile(0);
    sttile(0);
    __syncthreads();

    int buf = 0;
    for (int k0 = 0; k0 < K; k0 += 16, buf ^= 1) {
        const bool more = (k0 + 16) < K;
        if (more) ldtile(k0 + 16);

        const float* Ab = As[buf];
        const float* Wb = Ws[buf];
#pragma unroll
        for (int ks = 0; ks < 2; ++ks) {
            float af[4][4], bf[4][2];
            const int kr = ks * 8 + tig;
#pragma unroll
            for (int mt = 0; mt < 4; ++mt) {
                const int m = mbase + mt * 16 + g;
                af[mt][0] = Ab[kr * SA + m];
                af[mt][1] = Ab[kr * SA + m + 8];
                af[mt][2] = Ab[(kr + 4) * SA + m];
                af[mt][3] = Ab[(kr + 4) * SA + m + 8];
            }
#pragma unroll
            for (int nt = 0; nt < 4; ++nt) {
                const int n = nbase + nt * 8 + g;
                bf[nt][0] = Wb[kr * SA + n];
                bf[nt][1] = Wb[(kr + 4) * SA + n];
            }
#pragma unroll
            for (int mt = 0; mt < 4; ++mt)
#pragma unroll
                for (int nt = 0; nt < 4; ++nt)
                    mma_tf32(acc[mt][nt], af[mt][0], af[mt][1], af[mt][2], af[mt][3],
                             bf[nt][0], bf[nt][1]);
        }
        if (more) sttile(buf ^ 1);
        __syncthreads();
    }

#pragma unroll
    for (int mt = 0; mt < 4; ++mt) {
        const int row0 = by * 128 + mbase + mt * 16 + g;
#pragma unroll
        for (int nt = 0; nt < 4; ++nt) {
            const int col = bx * 128 + nbase + nt * 8 + tig * 2;
            float2 lo = make_float2(acc[mt][nt][0] * alpha, acc[mt][nt][1] * alpha);
            float2 hi = make_float2(acc[mt][nt][2] * alpha, acc[mt][nt][3] * alpha);
            *(float2*)(C + (size_t)row0 * Nc + col) = lo;
            *(float2*)(C + (size_t)(row0 + 8) * Nc + col) = hi;
        }
    }
}

// ---------------------------------------------------------------------------
// Tensor-core flash attention v2.
// grid: (L/128, B*NH), block 256 (8 warps; warp w owns query rows 16w..16w+15).
// P never touches smem: S C-fragments -> PV A-fragments via quad shfl.
// ---------------------------------------------------------------------------
#define FKS 68   // K tile stride
#define FVS 72   // V tile stride

__global__ void __launch_bounds__(256, 2)
flash_mma(const float* __restrict__ q, const float* __restrict__ k,
          const float* __restrict__ v, float* __restrict__ o)
{
    __shared__ float Ks[64 * FKS];
    __shared__ float Vs[64 * FVS];

    const int tid  = threadIdx.x;
    const int lane = tid & 31;
    const int w    = tid >> 5;
    const int g    = lane >> 2;
    const int tig  = lane & 3;

    const int bn = blockIdx.y;
    const int b  = bn >> 4;
    const int n  = bn & 15;
    const int f0 = blockIdx.x * 128;
    const int qr = 16 * w + g;

    // ---- Q fragments straight from gmem (one-time, tf32-rounded)
    const float* qrow0 = q + (size_t)(b * L_SEQ + f0 + qr) * D_MOD + n * HD;
    const float* qrow1 = qrow0 + (size_t)8 * D_MOD;
    float qa[8][4];
#pragma unroll
    for (int ks = 0; ks < 8; ++ks) {
        const int c = ks * 8 + tig;
        qa[ks][0] = tf32r(qrow0[c]);
        qa[ks][1] = tf32r(qrow1[c]);
        qa[ks][2] = tf32r(qrow0[c + 4]);
        qa[ks][3] = tf32r(qrow1[c + 4]);
    }

    float oacc[8][4];
#pragma unroll
    for (int nt = 0; nt < 8; ++nt)
#pragma unroll
        for (int i = 0; i < 4; ++i) oacc[nt][i] = 0.f;
    float m0 = -CUDART_INF_F, m1 = -CUDART_INF_F;
    float l0 = 0.f, l1 = 0.f;

    const float* kbase = k + (size_t)(b * L_SEQ) * D_MOD + n * HD;
    const float* vbase = v + (size_t)(b * L_SEQ) * D_MOD + n * HD;

    // fill mapping: row = tid>>2 (coalesced), col-quad = tid&3
    const int fr = tid >> 2;
    const int fc = (tid & 3) * 16;

    for (int t0 = 0; t0 < L_SEQ; t0 += 64) {
        const float* krp = kbase + (size_t)(t0 + fr) * D_MOD + fc;
        const float* vrp = vbase + (size_t)(t0 + fr) * D_MOD + fc;
#pragma unroll
        for (int j = 0; j < 4; ++j) {
            float4 tk = *(const float4*)(krp + j * 4);
            float4 tv = *(const float4*)(vrp + j * 4);
            float* kd = &Ks[fr * FKS + fc + j * 4];
            float* vd = &Vs[fr * FVS + fc + j * 4];
            kd[0] = tf32r(tk.x); kd[1] = tf32r(tk.y);
            kd[2] = tf32r(tk.z); kd[3] = tf32r(tk.w);
            vd[0] = tf32r(tv.x); vd[1] = tf32r(tv.y);
            vd[2] = tf32r(tv.z); vd[3] = tf32r(tv.w);
        }
        __syncthreads();

        // ---- S = Q @ K^T (16x64 per warp)
        float sacc[8][4];
#pragma unroll
        for (int nt = 0; nt < 8; ++nt)
#pragma unroll
            for (int i = 0; i < 4; ++i) sacc[nt][i] = 0.f;
#pragma unroll
        for (int nt = 0; nt < 8; ++nt) {
            const int trow = nt * 8 + g;
#pragma unroll
            for (int ks = 0; ks < 8; ++ks) {
                const float b0 = Ks[trow * FKS + ks * 8 + tig];
                const float b1 = Ks[trow * FKS + ks * 8 + tig + 4];
                mma_tf32(sacc[nt], qa[ks][0], qa[ks][1], qa[ks][2], qa[ks][3], b0, b1);
            }
        }

        // ---- online softmax (registers + quad shfl only)
        float tm0 = -CUDART_INF_F, tm1 = -CUDART_INF_F;
#pragma unroll
        for (int nt = 0; nt < 8; ++nt) {
            tm0 = fmaxf(tm0, fmaxf(sacc[nt][0], sacc[nt][1]));
            tm1 = fmaxf(tm1, fmaxf(sacc[nt][2], sacc[nt][3]));
        }
        tm0 = fmaxf(tm0, __shfl_xor_sync(0xffffffffu, tm0, 1));
        tm0 = fmaxf(tm0, __shfl_xor_sync(0xffffffffu, tm0, 2));
        tm1 = fmaxf(tm1, __shfl_xor_sync(0xffffffffu, tm1, 1));
        tm1 = fmaxf(tm1, __shfl_xor_sync(0xffffffffu, tm1, 2));

        const float nm0 = fmaxf(m0, tm0);
        const float nm1 = fmaxf(m1, tm1);
        const float sc0 = __expf(m0 - nm0);
        const float sc1 = __expf(m1 - nm1);
        m0 = nm0; m1 = nm1;
        l0 *= sc0; l1 *= sc1;
#pragma unroll
        for (int nt = 0; nt < 8; ++nt) {
            oacc[nt][0] *= sc0; oacc[nt][1] *= sc0;
            oacc[nt][2] *= sc1; oacc[nt][3] *= sc1;
        }

        float rs0 = 0.f, rs1 = 0.f;
#pragma unroll
        for (int nt = 0; nt < 8; ++nt) {
            const float p0 = __expf(sacc[nt][0] - m0);
            const float p1 = __expf(sacc[nt][1] - m0);
            const float p2 = __expf(sacc[nt][2] - m1);
            const float p3 = __expf(sacc[nt][3] - m1);
            rs0 += p0 + p1;  rs1 += p2 + p3;
            sacc[nt][0] = tf32r(p0);  sacc[nt][1] = tf32r(p1);
            sacc[nt][2] = tf32r(p2);  sacc[nt][3] = tf32r(p3);
        }
        rs0 += __shfl_xor_sync(0xffffffffu, rs0, 1);
        rs0 += __shfl_xor_sync(0xffffffffu, rs0, 2);
        rs1 += __shfl_xor_sync(0xffffffffu, rs1, 1);
        rs1 += __shfl_xor_sync(0xffffffffu, rs1, 2);
        l0 += rs0; l1 += rs1;

        // ---- O += P @ V ; P C-frag -> A-frag via quad shfl
        const int s0 = 4 * g + (tig >> 1);
        const int s1 = s0 + 2;
        const bool odd = (tig & 1);
#pragma unroll
        for (int kt = 0; kt < 8; ++kt) {
            const float e0 = __shfl_sync(0xffffffffu, sacc[kt][0], s0);
            const float e1 = __shfl_sync(0xffffffffu, sacc[kt][1], s0);
            const float e2 = __shfl_sync(0xffffffffu, sacc[kt][2], s0);
            const float e3 = __shfl_sync(0xffffffffu, sacc[kt][3], s0);
            const float f0v = __shfl_sync(0xffffffffu, sacc[kt][0], s1);
            const float f1v = __shfl_sync(0xffffffffu, sacc[kt][1], s1);
            const float f2v = __shfl_sync(0xffffffffu, sacc[kt][2], s1);
            const float f3v = __shfl_sync(0xffffffffu, sacc[kt][3], s1);
            const float pa0 = odd ? e1 : e0;
            const float pa1 = odd ? e3 : e2;
            const float pa2 = odd ? f1v : f0v;
            const float pa3 = odd ? f3v : f2v;
#pragma unroll
            for (int nt = 0; nt < 8; ++nt) {
                const float b0 = Vs[(kt * 8 + tig) * FVS + nt * 8 + g];
                const float b1 = Vs[(kt * 8 + tig + 4) * FVS + nt * 8 + g];
                mma_tf32(oacc[nt], pa0, pa1, pa2, pa3, b0, b1);
            }
        }
        __syncthreads();
    }

    // ---- epilogue
    const float inv0 = 1.f / l0;
    const float inv1 = 1.f / l1;
    float* ob = o + (size_t)(b * L_SEQ + f0 + qr) * D_MOD + n * HD;
#pragma unroll
    for (int nt = 0; nt < 8; ++nt) {
        const int col = nt * 8 + tig * 2;
        float2 lo = make_float2(oacc[nt][0] * inv0, oacc[nt][1] * inv0);
        float2 hi = make_float2(oacc[nt][2] * inv1, oacc[nt][3] * inv1);
        *(float2*)(ob + col) = lo;
        *(float2*)(ob + (size_t)8 * D_MOD + col) = hi;
    }
}

// ---------------------------------------------------------------------------
// kernel_launch
// inputs: [0]=query [1]=key [2]=value [3]=Wq [4]=Wk [5]=Wv [6]=Wo
// ---------------------------------------------------------------------------
extern "C" void kernel_launch(void* const* d_in, const int* in_sizes, int n_in,
                              void* d_out, int out_size)
{
    const float* qin = (const float*)d_in[0];
    const float* kin = (const float*)d_in[1];
    const float* vin = (const float*)d_in[2];
    const float* Wq  = (const float*)d_in[3];
    const float* Wk  = (const float*)d_in[4];
    const float* Wv  = (const float*)d_in[5];
    const float* Wo  = (const float*)d_in[6];
    float* out = (float*)d_out;

    float *dq, *dk, *dv, *dattn;
    cudaGetSymbolAddress((void**)&dq,    g_q);
    cudaGetSymbolAddress((void**)&dk,    g_k);
    cudaGetSymbolAddress((void**)&dv,    g_v);
    cudaGetSymbolAddress((void**)&dattn, g_attn);

    dim3 block(256);
    dim3 grid_qkv(D_MOD / 128, M_ROWS / 128, 3);
    dim3 grid_o(D_MOD / 128, M_ROWS / 128, 1);

    GemmTriple qkv;
    qkv.A[0] = qin; qkv.A[1] = kin; qkv.A[2] = vin;
    qkv.W[0] = Wq;  qkv.W[1] = Wk;  qkv.W[2] = Wv;
    qkv.C[0] = dq;  qkv.C[1] = dk;  qkv.C[2] = dv;
    qkv.alpha[0] = 0.125f;
    qkv.alpha[1] = 1.f;
    qkv.alpha[2] = 1.f;
    mma_gemm<3><<<grid_qkv, block>>>(qkv, M_ROWS, D_MOD, D_MOD);

    dim3 agrid(L_SEQ / 128, B_SZ * NH);
    flash_mma<<<agrid, 256>>>(dq, dk, dv, dattn);

    GemmTriple og;
    og.A[0] = dattn; og.W[0] = Wo; og.C[0] = out; og.alpha[0] = 1.f;
    og.A[1] = og.A[2] = nullptr; og.W[1] = og.W[2] = nullptr;
    og.C[1] = og.C[2] = nullptr; og.alpha[1] = og.alpha[2] = 0.f;
    mma_gemm<1><<<grid_o, block>>>(og, M_ROWS, D_MOD, D_MOD);
}

// round 5
// speedup vs baseline: 1.1981x; 1.1981x over previous
#include <cuda_runtime.h>
#include <math_constants.h>
#include <cstdint>

// Problem constants
#define B_SZ   2
#define L_SEQ  2048
#define D_MOD  1024
#define NH     16
#define HD     64
#define M_ROWS (B_SZ * L_SEQ)   // 4096

// Scratch (allocation-free rule: __device__ globals)
__device__ float g_q[M_ROWS * D_MOD];
__device__ float g_k[M_ROWS * D_MOD];
__device__ float g_v[M_ROWS * D_MOD];
__device__ float g_attn[M_ROWS * D_MOD];

// ---------------------------------------------------------------------------
// tf32 helpers
// ---------------------------------------------------------------------------
__device__ __forceinline__ float tf32r(float x) {
    uint32_t u;
    asm("cvt.rna.tf32.f32 %0, %1;" : "=r"(u) : "f"(x));
    return __uint_as_float(u);
}

__device__ __forceinline__ void mma_tf32(float c[4],
                                         float a0, float a1, float a2, float a3,
                                         float b0, float b1)
{
    asm volatile(
        "mma.sync.aligned.m16n8k8.row.col.f32.tf32.tf32.f32 "
        "{%0,%1,%2,%3},{%4,%5,%6,%7},{%8,%9},{%0,%1,%2,%3};"
        : "+f"(c[0]), "+f"(c[1]), "+f"(c[2]), "+f"(c[3])
        : "r"(__float_as_uint(a0)), "r"(__float_as_uint(a1)),
          "r"(__float_as_uint(a2)), "r"(__float_as_uint(a3)),
          "r"(__float_as_uint(b0)), "r"(__float_as_uint(b1)));
}

// ---------------------------------------------------------------------------
// tf32 tensor-core GEMM, 64x64 warp tiles (LDS:MMA = 1.0).
// C[M,Nc] = alpha * A[M,K] @ W[K,Nc] (row-major). BM=BN=128, BK=16.
// 128 threads = 4 warps in 2x2; ping-pong double-buffered smem.
// ---------------------------------------------------------------------------
struct GemmTriple {
    const float* A[3];
    const float* W[3];
    float*       C[3];
    float        alpha[3];
};

template <int NZ>
__global__ void __launch_bounds__(128)
mma_gemm(GemmTriple args, int M, int Nc, int K)
{
    constexpr int SA = 136;   // 136%32==8 -> conflict-free fragment reads
    __shared__ float As[2][16 * SA];  // [k][m]
    __shared__ float Ws[2][16 * SA];  // [k][n]

    const int z = (NZ > 1) ? blockIdx.z : 0;
    const float* __restrict__ A = args.A[z];
    const float* __restrict__ W = args.W[z];
    float* __restrict__ C = args.C[z];
    const float alpha = args.alpha[z];

    const int tid  = threadIdx.x;
    const int lane = tid & 31;
    const int w    = tid >> 5;
    const int g    = lane >> 2;
    const int tig  = lane & 3;
    const int mbase = (w >> 1) * 64;
    const int nbase = (w & 1) * 64;
    const int bx = blockIdx.x, by = blockIdx.y;

    // A fill mapping: 512 float4-slots; row = idx>>2 (0..127), c4 = idx&3
    // W fill mapping: 512 float4-slots; row = idx>>5 (0..15), col4 = idx&31
    const float* Abase = A + (size_t)(by * 128) * K;
    const float* Wbase = W + bx * 128;

    float acc[4][8][4];
#pragma unroll
    for (int mt = 0; mt < 4; ++mt)
#pragma unroll
        for (int nt = 0; nt < 8; ++nt)
#pragma unroll
            for (int i = 0; i < 4; ++i) acc[mt][nt][i] = 0.f;

    float4 ar[4], wr[4];
    auto ldtile = [&](int k0) {
#pragma unroll
        for (int i = 0; i < 4; ++i) {
            const int ai = tid + i * 128;
            ar[i] = *(const float4*)(Abase + (size_t)(ai >> 2) * K + k0 + (ai & 3) * 4);
            wr[i] = *(const float4*)(Wbase + (size_t)(k0 + (ai >> 5)) * Nc + (ai & 31) * 4);
        }
    };
    auto sttile = [&](int buf) {
        float* Ab = As[buf];
        float* Wb = Ws[buf];
#pragma unroll
        for (int i = 0; i < 4; ++i) {
            const int ai = tid + i * 128;
            const int arow = ai >> 2, ac4 = ai & 3;
            Ab[(ac4 * 4 + 0) * SA + arow] = tf32r(ar[i].x);
            Ab[(ac4 * 4 + 1) * SA + arow] = tf32r(ar[i].y);
            Ab[(ac4 * 4 + 2) * SA + arow] = tf32r(ar[i].z);
            Ab[(ac4 * 4 + 3) * SA + arow] = tf32r(ar[i].w);
            const int wrow = ai >> 5, wc = (ai & 31) * 4;
            float4 t;
            t.x = tf32r(wr[i].x); t.y = tf32r(wr[i].y);
            t.z = tf32r(wr[i].z); t.w = tf32r(wr[i].w);
            *(float4*)(&Wb[wrow * SA + wc]) = t;
        }
    };

    ldtile(0);
    sttile(0);
    __syncthreads();

    int buf = 0;
    for (int k0 = 0; k0 < K; k0 += 16, buf ^= 1) {
        const bool more = (k0 + 16) < K;
        if (more) ldtile(k0 + 16);

        const float* Ab = As[buf];
        const float* Wb = Ws[buf];
#pragma unroll
        for (int ks = 0; ks < 2; ++ks) {
            const int kr = ks * 8 + tig;
            float af[4][4], bf[8][2];
#pragma unroll
            for (int mt = 0; mt < 4; ++mt) {
                const int m = mbase + mt * 16 + g;
                af[mt][0] = Ab[kr * SA + m];
                af[mt][1] = Ab[kr * SA + m + 8];
                af[mt][2] = Ab[(kr + 4) * SA + m];
                af[mt][3] = Ab[(kr + 4) * SA + m + 8];
            }
#pragma unroll
            for (int nt = 0; nt < 8; ++nt) {
                const int n = nbase + nt * 8 + g;
                bf[nt][0] = Wb[kr * SA + n];
                bf[nt][1] = Wb[(kr + 4) * SA + n];
            }
#pragma unroll
            for (int mt = 0; mt < 4; ++mt)
#pragma unroll
                for (int nt = 0; nt < 8; ++nt)
                    mma_tf32(acc[mt][nt], af[mt][0], af[mt][1], af[mt][2], af[mt][3],
                             bf[nt][0], bf[nt][1]);
        }
        if (more) sttile(buf ^ 1);
        __syncthreads();
    }

#pragma unroll
    for (int mt = 0; mt < 4; ++mt) {
        const int row0 = by * 128 + mbase + mt * 16 + g;
#pragma unroll
        for (int nt = 0; nt < 8; ++nt) {
            const int col = bx * 128 + nbase + nt * 8 + tig * 2;
            float2 lo = make_float2(acc[mt][nt][0] * alpha, acc[mt][nt][1] * alpha);
            float2 hi = make_float2(acc[mt][nt][2] * alpha, acc[mt][nt][3] * alpha);
            *(float2*)(C + (size_t)row0 * Nc + col) = lo;
            *(float2*)(C + (size_t)(row0 + 8) * Nc + col) = hi;
        }
    }
}

// ---------------------------------------------------------------------------
// Flash attention (R1 version: tf32 mma.sync, 4 warps, smem P round-trip).
// grid: (L/64, B*NH), block 128; warp w owns query rows 16w..16w+15.
// ---------------------------------------------------------------------------
#define KS_STRIDE 68
#define VS_STRIDE 72

__global__ void __launch_bounds__(128, 3)
flash_mma(const float* __restrict__ q, const float* __restrict__ k,
          const float* __restrict__ v, float* __restrict__ o)
{
    __shared__ float buf0[64 * KS_STRIDE];  // Q -> K -> P
    __shared__ float buf1[64 * VS_STRIDE];  // V

    const int tid  = threadIdx.x;
    const int lane = tid & 31;
    const int w    = tid >> 5;
    const int g    = lane >> 2;
    const int tig  = lane & 3;

    const int bn = blockIdx.y;
    const int b  = bn >> 4;
    const int n  = bn & 15;
    const int f0 = blockIdx.x * 64;

    const float* qbase = q + (size_t)b * L_SEQ * D_MOD + (size_t)n * HD;
    const float* kbase = k + (size_t)b * L_SEQ * D_MOD + (size_t)n * HD;
    const float* vbase = v + (size_t)b * L_SEQ * D_MOD + (size_t)n * HD;

    for (int i = tid; i < 64 * 16; i += 128) {
        const int r = i >> 4;
        const int c = (i & 15) * 4;
        float4 t = *(const float4*)(qbase + (size_t)(f0 + r) * D_MOD + c);
        buf0[r * KS_STRIDE + c + 0] = tf32r(t.x);
        buf0[r * KS_STRIDE + c + 1] = tf32r(t.y);
        buf0[r * KS_STRIDE + c + 2] = tf32r(t.z);
        buf0[r * KS_STRIDE + c + 3] = tf32r(t.w);
    }
    __syncthreads();

    float qa[8][4];
    const int qr = 16 * w + g;
#pragma unroll
    for (int ks = 0; ks < 8; ++ks) {
        const int c = ks * 8 + tig;
        qa[ks][0] = buf0[qr * KS_STRIDE + c];
        qa[ks][1] = buf0[(qr + 8) * KS_STRIDE + c];
        qa[ks][2] = buf0[qr * KS_STRIDE + c + 4];
        qa[ks][3] = buf0[(qr + 8) * KS_STRIDE + c + 4];
    }
    __syncthreads();

    float oacc[8][4];
#pragma unroll
    for (int nt = 0; nt < 8; ++nt)
#pragma unroll
        for (int i = 0; i < 4; ++i) oacc[nt][i] = 0.f;
    float m0 = -CUDART_INF_F, m1 = -CUDART_INF_F;
    float l0 = 0.f, l1 = 0.f;

    for (int t0 = 0; t0 < L_SEQ; t0 += 64) {
        for (int i = tid; i < 64 * 16; i += 128) {
            const int r = i >> 4;
            const int c = (i & 15) * 4;
            float4 tk = *(const float4*)(kbase + (size_t)(t0 + r) * D_MOD + c);
            float4 tv = *(const float4*)(vbase + (size_t)(t0 + r) * D_MOD + c);
            buf0[r * KS_STRIDE + c + 0] = tf32r(tk.x);
            buf0[r * KS_STRIDE + c + 1] = tf32r(tk.y);
            buf0[r * KS_STRIDE + c + 2] = tf32r(tk.z);
            buf0[r * KS_STRIDE + c + 3] = tf32r(tk.w);
            buf1[r * VS_STRIDE + c + 0] = tf32r(tv.x);
            buf1[r * VS_STRIDE + c + 1] = tf32r(tv.y);
            buf1[r * VS_STRIDE + c + 2] = tf32r(tv.z);
            buf1[r * VS_STRIDE + c + 3] = tf32r(tv.w);
        }
        __syncthreads();

        float sacc[8][4];
#pragma unroll
        for (int nt = 0; nt < 8; ++nt)
#pragma unroll
            for (int i = 0; i < 4; ++i) sacc[nt][i] = 0.f;
#pragma unroll
        for (int nt = 0; nt < 8; ++nt) {
            const int trow = nt * 8 + g;
#pragma unroll
            for (int ks = 0; ks < 8; ++ks) {
                const float b0 = buf0[trow * KS_STRIDE + ks * 8 + tig];
                const float b1 = buf0[trow * KS_STRIDE + ks * 8 + tig + 4];
                mma_tf32(sacc[nt], qa[ks][0], qa[ks][1], qa[ks][2], qa[ks][3], b0, b1);
            }
        }
        __syncthreads();

        float tm0 = -CUDART_INF_F, tm1 = -CUDART_INF_F;
#pragma unroll
        for (int nt = 0; nt < 8; ++nt) {
            tm0 = fmaxf(tm0, fmaxf(sacc[nt][0], sacc[nt][1]));
            tm1 = fmaxf(tm1, fmaxf(sacc[nt][2], sacc[nt][3]));
        }
        tm0 = fmaxf(tm0, __shfl_xor_sync(0xffffffffu, tm0, 1));
        tm0 = fmaxf(tm0, __shfl_xor_sync(0xffffffffu, tm0, 2));
        tm1 = fmaxf(tm1, __shfl_xor_sync(0xffffffffu, tm1, 1));
        tm1 = fmaxf(tm1, __shfl_xor_sync(0xffffffffu, tm1, 2));

        const float nm0 = fmaxf(m0, tm0);
        const float nm1 = fmaxf(m1, tm1);
        const float sc0 = __expf(m0 - nm0);
        const float sc1 = __expf(m1 - nm1);
        m0 = nm0; m1 = nm1;
        l0 *= sc0; l1 *= sc1;
#pragma unroll
        for (int nt = 0; nt < 8; ++nt) {
            oacc[nt][0] *= sc0; oacc[nt][1] *= sc0;
            oacc[nt][2] *= sc1; oacc[nt][3] *= sc1;
        }

        float rs0 = 0.f, rs1 = 0.f;
#pragma unroll
        for (int nt = 0; nt < 8; ++nt) {
            const float p0 = __expf(sacc[nt][0] - m0);
            const float p1 = __expf(sacc[nt][1] - m0);
            const float p2 = __expf(sacc[nt][2] - m1);
            const float p3 = __expf(sacc[nt][3] - m1);
            rs0 += p0 + p1;
            rs1 += p2 + p3;
            const int col = nt * 8 + tig * 2;
            buf0[qr * KS_STRIDE + col]           = tf32r(p0);
            buf0[qr * KS_STRIDE + col + 1]       = tf32r(p1);
            buf0[(qr + 8) * KS_STRIDE + col]     = tf32r(p2);
            buf0[(qr + 8) * KS_STRIDE + col + 1] = tf32r(p3);
        }
        rs0 += __shfl_xor_sync(0xffffffffu, rs0, 1);
        rs0 += __shfl_xor_sync(0xffffffffu, rs0, 2);
        rs1 += __shfl_xor_sync(0xffffffffu, rs1, 1);
        rs1 += __shfl_xor_sync(0xffffffffu, rs1, 2);
        l0 += rs0; l1 += rs1;
        __syncwarp();

#pragma unroll
        for (int kt = 0; kt < 8; ++kt) {
            const int c = kt * 8 + tig;
            const float pa0 = buf0[qr * KS_STRIDE + c];
            const float pa1 = buf0[(qr + 8) * KS_STRIDE + c];
            const float pa2 = buf0[qr * KS_STRIDE + c + 4];
            const float pa3 = buf0[(qr + 8) * KS_STRIDE + c + 4];
#pragma unroll
            for (int nt = 0; nt < 8; ++nt) {
                const float b0 = buf1[(kt * 8 + tig) * VS_STRIDE + nt * 8 + g];
                const float b1 = buf1[(kt * 8 + tig + 4) * VS_STRIDE + nt * 8 + g];
                mma_tf32(oacc[nt], pa0, pa1, pa2, pa3, b0, b1);
            }
        }
        __syncthreads();
    }

    const float inv0 = 1.f / l0;
    const float inv1 = 1.f / l1;
    float* ob = o + (size_t)(b * L_SEQ + f0 + qr) * D_MOD + (size_t)n * HD;
#pragma unroll
    for (int nt = 0; nt < 8; ++nt) {
        const int col = nt * 8 + tig * 2;
        float2 lo = make_float2(oacc[nt][0] * inv0, oacc[nt][1] * inv0);
        float2 hi = make_float2(oacc[nt][2] * inv1, oacc[nt][3] * inv1);
        *(float2*)(ob + col) = lo;
        *(float2*)(ob + (size_t)8 * D_MOD + col) = hi;
    }
}

// ---------------------------------------------------------------------------
// kernel_launch
// inputs: [0]=query [1]=key [2]=value [3]=Wq [4]=Wk [5]=Wv [6]=Wo
// ---------------------------------------------------------------------------
extern "C" void kernel_launch(void* const* d_in, const int* in_sizes, int n_in,
                              void* d_out, int out_size)
{
    const float* qin = (const float*)d_in[0];
    const float* kin = (const float*)d_in[1];
    const float* vin = (const float*)d_in[2];
    const float* Wq  = (const float*)d_in[3];
    const float* Wk  = (const float*)d_in[4];
    const float* Wv  = (const float*)d_in[5];
    const float* Wo  = (const float*)d_in[6];
    float* out = (float*)d_out;

    float *dq, *dk, *dv, *dattn;
    cudaGetSymbolAddress((void**)&dq,    g_q);
    cudaGetSymbolAddress((void**)&dk,    g_k);
    cudaGetSymbolAddress((void**)&dv,    g_v);
    cudaGetSymbolAddress((void**)&dattn, g_attn);

    dim3 block(128);
    dim3 grid_qkv(D_MOD / 128, M_ROWS / 128, 3);
    dim3 grid_o(D_MOD / 128, M_ROWS / 128, 1);

    GemmTriple qkv;
    qkv.A[0] = qin; qkv.A[1] = kin; qkv.A[2] = vin;
    qkv.W[0] = Wq;  qkv.W[1] = Wk;  qkv.W[2] = Wv;
    qkv.C[0] = dq;  qkv.C[1] = dk;  qkv.C[2] = dv;
    qkv.alpha[0] = 0.125f;
    qkv.alpha[1] = 1.f;
    qkv.alpha[2] = 1.f;
    mma_gemm<3><<<grid_qkv, block>>>(qkv, M_ROWS, D_MOD, D_MOD);

    dim3 agrid(L_SEQ / 64, B_SZ * NH);
    flash_mma<<<agrid, 128>>>(dq, dk, dv, dattn);

    GemmTriple og;
    og.A[0] = dattn; og.W[0] = Wo; og.C[0] = out; og.alpha[0] = 1.f;
    og.A[1] = og.A[2] = nullptr; og.W[1] = og.W[2] = nullptr;
    og.C[1] = og.C[2] = nullptr; og.alpha[1] = og.alpha[2] = 0.f;
    mma_gemm<1><<<grid_o, block>>>(og, M_ROWS, D_MOD, D_MOD);
}

// round 8
// speedup vs baseline: 1.2926x; 1.0789x over previous
#include <cuda_runtime.h>
#include <math_constants.h>
#include <cstdint>

// Problem constants
#define B_SZ   2
#define L_SEQ  2048
#define D_MOD  1024
#define NH     16
#define HD     64
#define M_ROWS (B_SZ * L_SEQ)   // 4096

// Scratch (allocation-free rule: __device__ globals)
__device__ float g_q[M_ROWS * D_MOD];
__device__ float g_k[M_ROWS * D_MOD];
__device__ float g_v[M_ROWS * D_MOD];
__device__ float g_attn[M_ROWS * D_MOD];

// ---------------------------------------------------------------------------
// tf32 helpers
// ---------------------------------------------------------------------------
__device__ __forceinline__ float tf32r(float x) {
    uint32_t u;
    asm("cvt.rna.tf32.f32 %0, %1;" : "=r"(u) : "f"(x));
    return __uint_as_float(u);
}

__device__ __forceinline__ void mma_tf32(float c[4],
                                         float a0, float a1, float a2, float a3,
                                         float b0, float b1)
{
    asm volatile(
        "mma.sync.aligned.m16n8k8.row.col.f32.tf32.tf32.f32 "
        "{%0,%1,%2,%3},{%4,%5,%6,%7},{%8,%9},{%0,%1,%2,%3};"
        : "+f"(c[0]), "+f"(c[1]), "+f"(c[2]), "+f"(c[3])
        : "r"(__float_as_uint(a0)), "r"(__float_as_uint(a1)),
          "r"(__float_as_uint(a2)), "r"(__float_as_uint(a3)),
          "r"(__float_as_uint(b0)), "r"(__float_as_uint(b1)));
}

// ---------------------------------------------------------------------------
// tf32 tensor-core GEMM, 64x64 warp tiles (unchanged R4 winner).
// ---------------------------------------------------------------------------
struct GemmTriple {
    const float* A[3];
    const float* W[3];
    float*       C[3];
    float        alpha[3];
};

template <int NZ>
__global__ void __launch_bounds__(128)
mma_gemm(GemmTriple args, int M, int Nc, int K)
{
    constexpr int SA = 136;
    __shared__ float As[2][16 * SA];
    __shared__ float Ws[2][16 * SA];

    const int z = (NZ > 1) ? blockIdx.z : 0;
    const float* __restrict__ A = args.A[z];
    const float* __restrict__ W = args.W[z];
    float* __restrict__ C = args.C[z];
    const float alpha = args.alpha[z];

    const int tid  = threadIdx.x;
    const int lane = tid & 31;
    const int w    = tid >> 5;
    const int g    = lane >> 2;
    const int tig  = lane & 3;
    const int mbase = (w >> 1) * 64;
    const int nbase = (w & 1) * 64;
    const int bx = blockIdx.x, by = blockIdx.y;

    const float* Abase = A + (size_t)(by * 128) * K;
    const float* Wbase = W + bx * 128;

    float acc[4][8][4];
#pragma unroll
    for (int mt = 0; mt < 4; ++mt)
#pragma unroll
        for (int nt = 0; nt < 8; ++nt)
#pragma unroll
            for (int i = 0; i < 4; ++i) acc[mt][nt][i] = 0.f;

    float4 ar[4], wr[4];
    auto ldtile = [&](int k0) {
#pragma unroll
        for (int i = 0; i < 4; ++i) {
            const int ai = tid + i * 128;
            ar[i] = *(const float4*)(Abase + (size_t)(ai >> 2) * K + k0 + (ai & 3) * 4);
            wr[i] = *(const float4*)(Wbase + (size_t)(k0 + (ai >> 5)) * Nc + (ai & 31) * 4);
        }
    };
    auto sttile = [&](int buf) {
        float* Ab = As[buf];
        float* Wb = Ws[buf];
#pragma unroll
        for (int i = 0; i < 4; ++i) {
            const int ai = tid + i * 128;
            const int arow = ai >> 2, ac4 = ai & 3;
            Ab[(ac4 * 4 + 0) * SA + arow] = tf32r(ar[i].x);
            Ab[(ac4 * 4 + 1) * SA + arow] = tf32r(ar[i].y);
            Ab[(ac4 * 4 + 2) * SA + arow] = tf32r(ar[i].z);
            Ab[(ac4 * 4 + 3) * SA + arow] = tf32r(ar[i].w);
            const int wrow = ai >> 5, wc = (ai & 31) * 4;
            float4 t;
            t.x = tf32r(wr[i].x); t.y = tf32r(wr[i].y);
            t.z = tf32r(wr[i].z); t.w = tf32r(wr[i].w);
            *(float4*)(&Wb[wrow * SA + wc]) = t;
        }
    };

    ldtile(0);
    sttile(0);
    __syncthreads();

    int buf = 0;
    for (int k0 = 0; k0 < K; k0 += 16, buf ^= 1) {
        const bool more = (k0 + 16) < K;
        if (more) ldtile(k0 + 16);

        const float* Ab = As[buf];
        const float* Wb = Ws[buf];
#pragma unroll
        for (int ks = 0; ks < 2; ++ks) {
            const int kr = ks * 8 + tig;
            float af[4][4], bf[8][2];
#pragma unroll
            for (int mt = 0; mt < 4; ++mt) {
                const int m = mbase + mt * 16 + g;
                af[mt][0] = Ab[kr * SA + m];
                af[mt][1] = Ab[kr * SA + m + 8];
                af[mt][2] = Ab[(kr + 4) * SA + m];
                af[mt][3] = Ab[(kr + 4) * SA + m + 8];
            }
#pragma unroll
            for (int nt = 0; nt < 8; ++nt) {
                const int n = nbase + nt * 8 + g;
                bf[nt][0] = Wb[kr * SA + n];
                bf[nt][1] = Wb[(kr + 4) * SA + n];
            }
#pragma unroll
            for (int mt = 0; mt < 4; ++mt)
#pragma unroll
                for (int nt = 0; nt < 8; ++nt)
                    mma_tf32(acc[mt][nt], af[mt][0], af[mt][1], af[mt][2], af[mt][3],
                             bf[nt][0], bf[nt][1]);
        }
        if (more) sttile(buf ^ 1);
        __syncthreads();
    }

#pragma unroll
    for (int mt = 0; mt < 4; ++mt) {
        const int row0 = by * 128 + mbase + mt * 16 + g;
#pragma unroll
        for (int nt = 0; nt < 8; ++nt) {
            const int col = bx * 128 + nbase + nt * 8 + tig * 2;
            float2 lo = make_float2(acc[mt][nt][0] * alpha, acc[mt][nt][1] * alpha);
            float2 hi = make_float2(acc[mt][nt][2] * alpha, acc[mt][nt][3] * alpha);
            *(float2*)(C + (size_t)row0 * Nc + col) = lo;
            *(float2*)(C + (size_t)(row0 + 8) * Nc + col) = hi;
        }
    }
}

// ---------------------------------------------------------------------------
// Flash attention v3: 4 warps, 32 q-rows per warp (mt=2), 128 q-rows/CTA.
// B-fragments (K and V) reused across both mt -> smem ops per MMA cut 33%.
// grid: (L/128, B*NH), block 128.  DYNAMIC smem (53,248 B > 48KB static cap):
//   buf0 = 128x68 floats (K in rows 0..63 / P in all 128 rows, aliased)
//   buf1 = 64x72 floats  (V)
// ---------------------------------------------------------------------------
#define KS_STRIDE 68
#define VS_STRIDE 72
#define FLASH_SMEM_BYTES ((128 * KS_STRIDE + 64 * VS_STRIDE) * (int)sizeof(float))

__global__ void __launch_bounds__(128, 2)
flash_mma(const float* __restrict__ q, const float* __restrict__ k,
          const float* __restrict__ v, float* __restrict__ o)
{
    extern __shared__ float fsm[];
    float* buf0 = fsm;                       // 128 * KS_STRIDE
    float* buf1 = fsm + 128 * KS_STRIDE;     // 64 * VS_STRIDE

    const int tid  = threadIdx.x;
    const int lane = tid & 31;
    const int w    = tid >> 5;
    const int g    = lane >> 2;
    const int tig  = lane & 3;

    const int bn = blockIdx.y;
    const int b  = bn >> 4;
    const int n  = bn & 15;
    const int f0 = blockIdx.x * 128;

    const float* kbase = k + (size_t)b * L_SEQ * D_MOD + (size_t)n * HD;
    const float* vbase = v + (size_t)b * L_SEQ * D_MOD + (size_t)n * HD;

    // per-warp local P rows: pr[mt] = 32w + 16mt + g (and +8)
    const int pr0 = 32 * w + g;         // mt=0
    const int pr1 = 32 * w + 16 + g;    // mt=1

    // ---- Q fragments directly from gmem (one-time, tf32-rounded)
    float qa[2][8][4];
    {
        const float* q00 = q + (size_t)(b * L_SEQ + f0 + pr0) * D_MOD + n * HD;
        const float* q01 = q00 + (size_t)8 * D_MOD;
        const float* q10 = q + (size_t)(b * L_SEQ + f0 + pr1) * D_MOD + n * HD;
        const float* q11 = q10 + (size_t)8 * D_MOD;
#pragma unroll
        for (int ks = 0; ks < 8; ++ks) {
            const int c = ks * 8 + tig;
            qa[0][ks][0] = tf32r(q00[c]);
            qa[0][ks][1] = tf32r(q01[c]);
            qa[0][ks][2] = tf32r(q00[c + 4]);
            qa[0][ks][3] = tf32r(q01[c + 4]);
            qa[1][ks][0] = tf32r(q10[c]);
            qa[1][ks][1] = tf32r(q11[c]);
            qa[1][ks][2] = tf32r(q10[c + 4]);
            qa[1][ks][3] = tf32r(q11[c + 4]);
        }
    }

    float oacc[2][8][4];
#pragma unroll
    for (int mt = 0; mt < 2; ++mt)
#pragma unroll
        for (int nt = 0; nt < 8; ++nt)
#pragma unroll
            for (int i = 0; i < 4; ++i) oacc[mt][nt][i] = 0.f;
    float mrow[2][2] = {{-CUDART_INF_F, -CUDART_INF_F}, {-CUDART_INF_F, -CUDART_INF_F}};
    float lrow[2][2] = {{0.f, 0.f}, {0.f, 0.f}};

    for (int t0 = 0; t0 < L_SEQ; t0 += 64) {
        // ---- cooperative K/V tile load (64 rows x 64 cols each)
        for (int i = tid; i < 64 * 16; i += 128) {
            const int r = i >> 4;
            const int c = (i & 15) * 4;
            float4 tk = *(const float4*)(kbase + (size_t)(t0 + r) * D_MOD + c);
            float4 tv = *(const float4*)(vbase + (size_t)(t0 + r) * D_MOD + c);
            buf0[r * KS_STRIDE + c + 0] = tf32r(tk.x);
            buf0[r * KS_STRIDE + c + 1] = tf32r(tk.y);
            buf0[r * KS_STRIDE + c + 2] = tf32r(tk.z);
            buf0[r * KS_STRIDE + c + 3] = tf32r(tk.w);
            buf1[r * VS_STRIDE + c + 0] = tf32r(tv.x);
            buf1[r * VS_STRIDE + c + 1] = tf32r(tv.y);
            buf1[r * VS_STRIDE + c + 2] = tf32r(tv.z);
            buf1[r * VS_STRIDE + c + 3] = tf32r(tv.w);
        }
        __syncthreads();

        // ---- S = Q @ K^T : 32x64 per warp, B frags reused across mt
        float sacc[2][8][4];
#pragma unroll
        for (int mt = 0; mt < 2; ++mt)
#pragma unroll
            for (int nt = 0; nt < 8; ++nt)
#pragma unroll
                for (int i = 0; i < 4; ++i) sacc[mt][nt][i] = 0.f;
#pragma unroll
        for (int nt = 0; nt < 8; ++nt) {
            const int trow = nt * 8 + g;
#pragma unroll
            for (int ks = 0; ks < 8; ++ks) {
                const float b0 = buf0[trow * KS_STRIDE + ks * 8 + tig];
                const float b1 = buf0[trow * KS_STRIDE + ks * 8 + tig + 4];
                mma_tf32(sacc[0][nt], qa[0][ks][0], qa[0][ks][1], qa[0][ks][2], qa[0][ks][3], b0, b1);
                mma_tf32(sacc[1][nt], qa[1][ks][0], qa[1][ks][1], qa[1][ks][2], qa[1][ks][3], b0, b1);
            }
        }
        __syncthreads();   // all warps done reading K before P overwrites buf0

        // ---- online softmax per mt, write P to smem
#pragma unroll
        for (int mt = 0; mt < 2; ++mt) {
            const int pr = (mt == 0) ? pr0 : pr1;
            float tm0 = -CUDART_INF_F, tm1 = -CUDART_INF_F;
#pragma unroll
            for (int nt = 0; nt < 8; ++nt) {
                tm0 = fmaxf(tm0, fmaxf(sacc[mt][nt][0], sacc[mt][nt][1]));
                tm1 = fmaxf(tm1, fmaxf(sacc[mt][nt][2], sacc[mt][nt][3]));
            }
            tm0 = fmaxf(tm0, __shfl_xor_sync(0xffffffffu, tm0, 1));
            tm0 = fmaxf(tm0, __shfl_xor_sync(0xffffffffu, tm0, 2));
            tm1 = fmaxf(tm1, __shfl_xor_sync(0xffffffffu, tm1, 1));
            tm1 = fmaxf(tm1, __shfl_xor_sync(0xffffffffu, tm1, 2));

            const float nm0 = fmaxf(mrow[mt][0], tm0);
            const float nm1 = fmaxf(mrow[mt][1], tm1);
            const float sc0 = __expf(mrow[mt][0] - nm0);
            const float sc1 = __expf(mrow[mt][1] - nm1);
            mrow[mt][0] = nm0; mrow[mt][1] = nm1;
            lrow[mt][0] *= sc0; lrow[mt][1] *= sc1;
#pragma unroll
            for (int nt = 0; nt < 8; ++nt) {
                oacc[mt][nt][0] *= sc0; oacc[mt][nt][1] *= sc0;
                oacc[mt][nt][2] *= sc1; oacc[mt][nt][3] *= sc1;
            }

            float rs0 = 0.f, rs1 = 0.f;
#pragma unroll
            for (int nt = 0; nt < 8; ++nt) {
                const float p0 = __expf(sacc[mt][nt][0] - nm0);
                const float p1 = __expf(sacc[mt][nt][1] - nm0);
                const float p2 = __expf(sacc[mt][nt][2] - nm1);
                const float p3 = __expf(sacc[mt][nt][3] - nm1);
                rs0 += p0 + p1;  rs1 += p2 + p3;
                const int col = nt * 8 + tig * 2;
                buf0[pr * KS_STRIDE + col]           = tf32r(p0);
                buf0[pr * KS_STRIDE + col + 1]       = tf32r(p1);
                buf0[(pr + 8) * KS_STRIDE + col]     = tf32r(p2);
                buf0[(pr + 8) * KS_STRIDE + col + 1] = tf32r(p3);
            }
            rs0 += __shfl_xor_sync(0xffffffffu, rs0, 1);
            rs0 += __shfl_xor_sync(0xffffffffu, rs0, 2);
            rs1 += __shfl_xor_sync(0xffffffffu, rs1, 1);
            rs1 += __shfl_xor_sync(0xffffffffu, rs1, 2);
            lrow[mt][0] += rs0; lrow[mt][1] += rs1;
        }
        __syncwarp();   // P rows are warp-private

        // ---- O += P @ V : V frags reused across mt
#pragma unroll
        for (int kt = 0; kt < 8; ++kt) {
            const int c = kt * 8 + tig;
            const float a00 = buf0[pr0 * KS_STRIDE + c];
            const float a01 = buf0[(pr0 + 8) * KS_STRIDE + c];
            const float a02 = buf0[pr0 * KS_STRIDE + c + 4];
            const float a03 = buf0[(pr0 + 8) * KS_STRIDE + c + 4];
            const float a10 = buf0[pr1 * KS_STRIDE + c];
            const float a11 = buf0[(pr1 + 8) * KS_STRIDE + c];
            const float a12 = buf0[pr1 * KS_STRIDE + c + 4];
            const float a13 = buf0[(pr1 + 8) * KS_STRIDE + c + 4];
#pragma unroll
            for (int nt = 0; nt < 8; ++nt) {
                const float b0 = buf1[(kt * 8 + tig) * VS_STRIDE + nt * 8 + g];
                const float b1 = buf1[(kt * 8 + tig + 4) * VS_STRIDE + nt * 8 + g];
                mma_tf32(oacc[0][nt], a00, a01, a02, a03, b0, b1);
                mma_tf32(oacc[1][nt], a10, a11, a12, a13, b0, b1);
            }
        }
        __syncthreads();   // all warps done with P/V before next tile load
    }

    // ---- epilogue
#pragma unroll
    for (int mt = 0; mt < 2; ++mt) {
        const int pr = (mt == 0) ? pr0 : pr1;
        const float inv0 = 1.f / lrow[mt][0];
        const float inv1 = 1.f / lrow[mt][1];
        float* ob = o + (size_t)(b * L_SEQ + f0 + pr) * D_MOD + (size_t)n * HD;
#pragma unroll
        for (int nt = 0; nt < 8; ++nt) {
            const int col = nt * 8 + tig * 2;
            float2 lo = make_float2(oacc[mt][nt][0] * inv0, oacc[mt][nt][1] * inv0);
            float2 hi = make_float2(oacc[mt][nt][2] * inv1, oacc[mt][nt][3] * inv1);
            *(float2*)(ob + col) = lo;
            *(float2*)(ob + (size_t)8 * D_MOD + col) = hi;
        }
    }
}

// ---------------------------------------------------------------------------
// kernel_launch
// inputs: [0]=query [1]=key [2]=value [3]=Wq [4]=Wk [5]=Wv [6]=Wo
// ---------------------------------------------------------------------------
extern "C" void kernel_launch(void* const* d_in, const int* in_sizes, int n_in,
                              void* d_out, int out_size)
{
    const float* qin = (const float*)d_in[0];
    const float* kin = (const float*)d_in[1];
    const float* vin = (const float*)d_in[2];
    const float* Wq  = (const float*)d_in[3];
    const float* Wk  = (const float*)d_in[4];
    const float* Wv  = (const float*)d_in[5];
    const float* Wo  = (const float*)d_in[6];
    float* out = (float*)d_out;

    float *dq, *dk, *dv, *dattn;
    cudaGetSymbolAddress((void**)&dq,    g_q);
    cudaGetSymbolAddress((void**)&dk,    g_k);
    cudaGetSymbolAddress((void**)&dv,    g_v);
    cudaGetSymbolAddress((void**)&dattn, g_attn);

    // raise dynamic-smem cap for flash (53,248 B > default 48KB) — idempotent
    cudaFuncSetAttribute(flash_mma, cudaFuncAttributeMaxDynamicSharedMemorySize,
                         FLASH_SMEM_BYTES);

    dim3 block(128);
    dim3 grid_qkv(D_MOD / 128, M_ROWS / 128, 3);
    dim3 grid_o(D_MOD / 128, M_ROWS / 128, 1);

    GemmTriple qkv;
    qkv.A[0] = qin; qkv.A[1] = kin; qkv.A[2] = vin;
    qkv.W[0] = Wq;  qkv.W[1] = Wk;  qkv.W[2] = Wv;
    qkv.C[0] = dq;  qkv.C[1] = dk;  qkv.C[2] = dv;
    qkv.alpha[0] = 0.125f;
    qkv.alpha[1] = 1.f;
    qkv.alpha[2] = 1.f;
    mma_gemm<3><<<grid_qkv, block>>>(qkv, M_ROWS, D_MOD, D_MOD);

    dim3 agrid(L_SEQ / 128, B_SZ * NH);
    flash_mma<<<agrid, 128, FLASH_SMEM_BYTES>>>(dq, dk, dv, dattn);

    GemmTriple og;
    og.A[0] = dattn; og.W[0] = Wo; og.C[0] = out; og.alpha[0] = 1.f;
    og.A[1] = og.A[2] = nullptr; og.W[1] = og.W[2] = nullptr;
    og.C[1] = og.C[2] = nullptr; og.alpha[1] = og.alpha[2] = 0.f;
    mma_gemm<1><<<grid_o, block>>>(og, M_ROWS, D_MOD, D_MOD);
}

// round 9
// speedup vs baseline: 1.3570x; 1.0498x over previous
#include <cuda_runtime.h>
#include <math_constants.h>
#include <cstdint>

// Problem constants
#define B_SZ   2
#define L_SEQ  2048
#define D_MOD  1024
#define NH     16
#define HD     64
#define M_ROWS (B_SZ * L_SEQ)   // 4096

// Scratch (allocation-free rule: __device__ globals)
__device__ float g_q[M_ROWS * D_MOD];
__device__ float g_k[M_ROWS * D_MOD];
__device__ float g_v[M_ROWS * D_MOD];
__device__ float g_attn[M_ROWS * D_MOD];

// ---------------------------------------------------------------------------
// tf32 helpers
// ---------------------------------------------------------------------------
__device__ __forceinline__ float tf32r(float x) {
    uint32_t u;
    asm("cvt.rna.tf32.f32 %0, %1;" : "=r"(u) : "f"(x));
    return __uint_as_float(u);
}

__device__ __forceinline__ void mma_tf32(float c[4],
                                         float a0, float a1, float a2, float a3,
                                         float b0, float b1)
{
    asm volatile(
        "mma.sync.aligned.m16n8k8.row.col.f32.tf32.tf32.f32 "
        "{%0,%1,%2,%3},{%4,%5,%6,%7},{%8,%9},{%0,%1,%2,%3};"
        : "+f"(c[0]), "+f"(c[1]), "+f"(c[2]), "+f"(c[3])
        : "r"(__float_as_uint(a0)), "r"(__float_as_uint(a1)),
          "r"(__float_as_uint(a2)), "r"(__float_as_uint(a3)),
          "r"(__float_as_uint(b0)), "r"(__float_as_uint(b1)));
}

__device__ __forceinline__ void cp_async16(uint32_t saddr, const void* gptr) {
    asm volatile("cp.async.cg.shared.global [%0], [%1], 16;"
                 :: "r"(saddr), "l"(gptr) : "memory");
}

// ---------------------------------------------------------------------------
// tf32 tensor-core GEMM v3: cp.async double-buffered, BK=32, 64x64 warp tiles.
// C[M,Nc] = alpha * A[M,K] @ W[K,Nc] (row-major). 128 threads = 4 warps (2x2).
// smem (dynamic): A [128][36] fp32 raw x2, W [32][136] fp32 raw x2 (70KB).
// tf32 rounding applied at fragment read (identical numerics to store-side).
// ---------------------------------------------------------------------------
struct GemmTriple {
    const float* A[3];
    const float* W[3];
    float*       C[3];
    float        alpha[3];
};

#define BKG   32
#define ASTR  36     // A row stride (floats): bank(g*36+tig)=4g+tig -> distinct
#define WSTR  136    // W row stride (floats): bank(tig*136+g)=8tig+g -> distinct
#define A_BUF (128 * ASTR)
#define W_BUF (BKG * WSTR)
#define GEMM_SMEM_BYTES ((2 * A_BUF + 2 * W_BUF) * (int)sizeof(float))

template <int NZ>
__global__ void __launch_bounds__(128)
mma_gemm(GemmTriple args, int M, int Nc, int K)
{
    extern __shared__ float gsm[];
    const uint32_t sbase = (uint32_t)__cvta_generic_to_shared(gsm);

    const int z = (NZ > 1) ? blockIdx.z : 0;
    const float* __restrict__ A = args.A[z];
    const float* __restrict__ W = args.W[z];
    float* __restrict__ C = args.C[z];
    const float alpha = args.alpha[z];

    const int tid  = threadIdx.x;
    const int lane = tid & 31;
    const int w    = tid >> 5;
    const int g    = lane >> 2;
    const int tig  = lane & 3;
    const int mbase = (w >> 1) * 64;
    const int nbase = (w & 1) * 64;
    const int bx = blockIdx.x, by = blockIdx.y;

    const float* Abase = A + (size_t)(by * 128) * K;
    const float* Wbase = W + bx * 128;

    float acc[4][8][4];
#pragma unroll
    for (int mt = 0; mt < 4; ++mt)
#pragma unroll
        for (int nt = 0; nt < 8; ++nt)
#pragma unroll
            for (int i = 0; i < 4; ++i) acc[mt][nt][i] = 0.f;

    // stage issue: 1024 A-chunks (16B) + 1024 W-chunks, 8 each per thread
    auto issue = [&](int k0, int b) {
        const uint32_t abuf = sbase + (uint32_t)(b * A_BUF) * 4u;
        const uint32_t wbuf = sbase + (uint32_t)(2 * A_BUF + b * W_BUF) * 4u;
#pragma unroll
        for (int i = 0; i < 8; ++i) {
            const int a = tid + i * 128;
            const int r = a >> 3, c4 = a & 7;
            cp_async16(abuf + (uint32_t)(r * ASTR + c4 * 4) * 4u,
                       Abase + (size_t)r * K + k0 + c4 * 4);
            const int krow = a >> 5, c = (a & 31) * 4;
            cp_async16(wbuf + (uint32_t)(krow * WSTR + c) * 4u,
                       Wbase + (size_t)(k0 + krow) * Nc + c);
        }
        asm volatile("cp.async.commit_group;" ::: "memory");
    };

    const int NST = K / BKG;
    issue(0, 0);
    issue(BKG, 1);

    int buf = 0;
    for (int s = 0; s < NST; ++s, buf ^= 1) {
        if (s + 1 < NST)
            asm volatile("cp.async.wait_group 1;" ::: "memory");
        else
            asm volatile("cp.async.wait_group 0;" ::: "memory");
        __syncthreads();

        const float* Ab = gsm + buf * A_BUF;
        const float* Wb = gsm + 2 * A_BUF + buf * W_BUF;
#pragma unroll
        for (int ks = 0; ks < 4; ++ks) {
            const int kr = ks * 8 + tig;
            float af[4][4], bf[8][2];
#pragma unroll
            for (int mt = 0; mt < 4; ++mt) {
                const int m = mbase + mt * 16 + g;
                af[mt][0] = tf32r(Ab[m * ASTR + kr]);
                af[mt][1] = tf32r(Ab[(m + 8) * ASTR + kr]);
                af[mt][2] = tf32r(Ab[m * ASTR + kr + 4]);
                af[mt][3] = tf32r(Ab[(m + 8) * ASTR + kr + 4]);
            }
#pragma unroll
            for (int nt = 0; nt < 8; ++nt) {
                const int n = nbase + nt * 8 + g;
                bf[nt][0] = tf32r(Wb[kr * WSTR + n]);
                bf[nt][1] = tf32r(Wb[(kr + 4) * WSTR + n]);
            }
#pragma unroll
            for (int mt = 0; mt < 4; ++mt)
#pragma unroll
                for (int nt = 0; nt < 8; ++nt)
                    mma_tf32(acc[mt][nt], af[mt][0], af[mt][1], af[mt][2], af[mt][3],
                             bf[nt][0], bf[nt][1]);
        }
        __syncthreads();
        if (s + 2 < NST) issue((s + 2) * BKG, buf);
    }

#pragma unroll
    for (int mt = 0; mt < 4; ++mt) {
        const int row0 = by * 128 + mbase + mt * 16 + g;
#pragma unroll
        for (int nt = 0; nt < 8; ++nt) {
            const int col = bx * 128 + nbase + nt * 8 + tig * 2;
            float2 lo = make_float2(acc[mt][nt][0] * alpha, acc[mt][nt][1] * alpha);
            float2 hi = make_float2(acc[mt][nt][2] * alpha, acc[mt][nt][3] * alpha);
            *(float2*)(C + (size_t)row0 * Nc + col) = lo;
            *(float2*)(C + (size_t)(row0 + 8) * Nc + col) = hi;
        }
    }
}

// ---------------------------------------------------------------------------
// Flash attention v3 (unchanged R7 winner): 4 warps, 32 q-rows/warp, dyn smem.
// ---------------------------------------------------------------------------
#define KS_STRIDE 68
#define VS_STRIDE 72
#define FLASH_SMEM_BYTES ((128 * KS_STRIDE + 64 * VS_STRIDE) * (int)sizeof(float))

__global__ void __launch_bounds__(128, 2)
flash_mma(const float* __restrict__ q, const float* __restrict__ k,
          const float* __restrict__ v, float* __restrict__ o)
{
    extern __shared__ float fsm[];
    float* buf0 = fsm;                       // 128 * KS_STRIDE
    float* buf1 = fsm + 128 * KS_STRIDE;     // 64 * VS_STRIDE

    const int tid  = threadIdx.x;
    const int lane = tid & 31;
    const int w    = tid >> 5;
    const int g    = lane >> 2;
    const int tig  = lane & 3;

    const int bn = blockIdx.y;
    const int b  = bn >> 4;
    const int n  = bn & 15;
    const int f0 = blockIdx.x * 128;

    const float* kbase = k + (size_t)b * L_SEQ * D_MOD + (size_t)n * HD;
    const float* vbase = v + (size_t)b * L_SEQ * D_MOD + (size_t)n * HD;

    const int pr0 = 32 * w + g;
    const int pr1 = 32 * w + 16 + g;

    float qa[2][8][4];
    {
        const float* q00 = q + (size_t)(b * L_SEQ + f0 + pr0) * D_MOD + n * HD;
        const float* q01 = q00 + (size_t)8 * D_MOD;
        const float* q10 = q + (size_t)(b * L_SEQ + f0 + pr1) * D_MOD + n * HD;
        const float* q11 = q10 + (size_t)8 * D_MOD;
#pragma unroll
        for (int ks = 0; ks < 8; ++ks) {
            const int c = ks * 8 + tig;
            qa[0][ks][0] = tf32r(q00[c]);
            qa[0][ks][1] = tf32r(q01[c]);
            qa[0][ks][2] = tf32r(q00[c + 4]);
            qa[0][ks][3] = tf32r(q01[c + 4]);
            qa[1][ks][0] = tf32r(q10[c]);
            qa[1][ks][1] = tf32r(q11[c]);
            qa[1][ks][2] = tf32r(q10[c + 4]);
            qa[1][ks][3] = tf32r(q11[c + 4]);
        }
    }

    float oacc[2][8][4];
#pragma unroll
    for (int mt = 0; mt < 2; ++mt)
#pragma unroll
        for (int nt = 0; nt < 8; ++nt)
#pragma unroll
            for (int i = 0; i < 4; ++i) oacc[mt][nt][i] = 0.f;
    float mrow[2][2] = {{-CUDART_INF_F, -CUDART_INF_F}, {-CUDART_INF_F, -CUDART_INF_F}};
    float lrow[2][2] = {{0.f, 0.f}, {0.f, 0.f}};

    for (int t0 = 0; t0 < L_SEQ; t0 += 64) {
        for (int i = tid; i < 64 * 16; i += 128) {
            const int r = i >> 4;
            const int c = (i & 15) * 4;
            float4 tk = *(const float4*)(kbase + (size_t)(t0 + r) * D_MOD + c);
            float4 tv = *(const float4*)(vbase + (size_t)(t0 + r) * D_MOD + c);
            buf0[r * KS_STRIDE + c + 0] = tf32r(tk.x);
            buf0[r * KS_STRIDE + c + 1] = tf32r(tk.y);
            buf0[r * KS_STRIDE + c + 2] = tf32r(tk.z);
            buf0[r * KS_STRIDE + c + 3] = tf32r(tk.w);
            buf1[r * VS_STRIDE + c + 0] = tf32r(tv.x);
            buf1[r * VS_STRIDE + c + 1] = tf32r(tv.y);
            buf1[r * VS_STRIDE + c + 2] = tf32r(tv.z);
            buf1[r * VS_STRIDE + c + 3] = tf32r(tv.w);
        }
        __syncthreads();

        float sacc[2][8][4];
#pragma unroll
        for (int mt = 0; mt < 2; ++mt)
#pragma unroll
            for (int nt = 0; nt < 8; ++nt)
#pragma unroll
                for (int i = 0; i < 4; ++i) sacc[mt][nt][i] = 0.f;
#pragma unroll
        for (int nt = 0; nt < 8; ++nt) {
            const int trow = nt * 8 + g;
#pragma unroll
            for (int ks = 0; ks < 8; ++ks) {
                const float b0 = buf0[trow * KS_STRIDE + ks * 8 + tig];
                const float b1 = buf0[trow * KS_STRIDE + ks * 8 + tig + 4];
                mma_tf32(sacc[0][nt], qa[0][ks][0], qa[0][ks][1], qa[0][ks][2], qa[0][ks][3], b0, b1);
                mma_tf32(sacc[1][nt], qa[1][ks][0], qa[1][ks][1], qa[1][ks][2], qa[1][ks][3], b0, b1);
            }
        }
        __syncthreads();

#pragma unroll
        for (int mt = 0; mt < 2; ++mt) {
            const int pr = (mt == 0) ? pr0 : pr1;
            float tm0 = -CUDART_INF_F, tm1 = -CUDART_INF_F;
#pragma unroll
            for (int nt = 0; nt < 8; ++nt) {
                tm0 = fmaxf(tm0, fmaxf(sacc[mt][nt][0], sacc[mt][nt][1]));
                tm1 = fmaxf(tm1, fmaxf(sacc[mt][nt][2], sacc[mt][nt][3]));
            }
            tm0 = fmaxf(tm0, __shfl_xor_sync(0xffffffffu, tm0, 1));
            tm0 = fmaxf(tm0, __shfl_xor_sync(0xffffffffu, tm0, 2));
            tm1 = fmaxf(tm1, __shfl_xor_sync(0xffffffffu, tm1, 1));
            tm1 = fmaxf(tm1, __shfl_xor_sync(0xffffffffu, tm1, 2));

            const float nm0 = fmaxf(mrow[mt][0], tm0);
            const float nm1 = fmaxf(mrow[mt][1], tm1);
            const float sc0 = __expf(mrow[mt][0] - nm0);
            const float sc1 = __expf(mrow[mt][1] - nm1);
            mrow[mt][0] = nm0; mrow[mt][1] = nm1;
            lrow[mt][0] *= sc0; lrow[mt][1] *= sc1;
#pragma unroll
            for (int nt = 0; nt < 8; ++nt) {
                oacc[mt][nt][0] *= sc0; oacc[mt][nt][1] *= sc0;
                oacc[mt][nt][2] *= sc1; oacc[mt][nt][3] *= sc1;
            }

            float rs0 = 0.f, rs1 = 0.f;
#pragma unroll
            for (int nt = 0; nt < 8; ++nt) {
                const float p0 = __expf(sacc[mt][nt][0] - nm0);
                const float p1 = __expf(sacc[mt][nt][1] - nm0);
                const float p2 = __expf(sacc[mt][nt][2] - nm1);
                const float p3 = __expf(sacc[mt][nt][3] - nm1);
                rs0 += p0 + p1;  rs1 += p2 + p3;
                const int col = nt * 8 + tig * 2;
                buf0[pr * KS_STRIDE + col]           = tf32r(p0);
                buf0[pr * KS_STRIDE + col + 1]       = tf32r(p1);
                buf0[(pr + 8) * KS_STRIDE + col]     = tf32r(p2);
                buf0[(pr + 8) * KS_STRIDE + col + 1] = tf32r(p3);
            }
            rs0 += __shfl_xor_sync(0xffffffffu, rs0, 1);
            rs0 += __shfl_xor_sync(0xffffffffu, rs0, 2);
            rs1 += __shfl_xor_sync(0xffffffffu, rs1, 1);
            rs1 += __shfl_xor_sync(0xffffffffu, rs1, 2);
            lrow[mt][0] += rs0; lrow[mt][1] += rs1;
        }
        __syncwarp();

#pragma unroll
        for (int kt = 0; kt < 8; ++kt) {
            const int c = kt * 8 + tig;
            const float a00 = buf0[pr0 * KS_STRIDE + c];
            const float a01 = buf0[(pr0 + 8) * KS_STRIDE + c];
            const float a02 = buf0[pr0 * KS_STRIDE + c + 4];
            const float a03 = buf0[(pr0 + 8) * KS_STRIDE + c + 4];
            const float a10 = buf0[pr1 * KS_STRIDE + c];
            const float a11 = buf0[(pr1 + 8) * KS_STRIDE + c];
            const float a12 = buf0[pr1 * KS_STRIDE + c + 4];
            const float a13 = buf0[(pr1 + 8) * KS_STRIDE + c + 4];
#pragma unroll
            for (int nt = 0; nt < 8; ++nt) {
                const float b0 = buf1[(kt * 8 + tig) * VS_STRIDE + nt * 8 + g];
                const float b1 = buf1[(kt * 8 + tig + 4) * VS_STRIDE + nt * 8 + g];
                mma_tf32(oacc[0][nt], a00, a01, a02, a03, b0, b1);
                mma_tf32(oacc[1][nt], a10, a11, a12, a13, b0, b1);
            }
        }
        __syncthreads();
    }

#pragma unroll
    for (int mt = 0; mt < 2; ++mt) {
        const int pr = (mt == 0) ? pr0 : pr1;
        const float inv0 = 1.f / lrow[mt][0];
        const float inv1 = 1.f / lrow[mt][1];
        float* ob = o + (size_t)(b * L_SEQ + f0 + pr) * D_MOD + (size_t)n * HD;
#pragma unroll
        for (int nt = 0; nt < 8; ++nt) {
            const int col = nt * 8 + tig * 2;
            float2 lo = make_float2(oacc[mt][nt][0] * inv0, oacc[mt][nt][1] * inv0);
            float2 hi = make_float2(oacc[mt][nt][2] * inv1, oacc[mt][nt][3] * inv1);
            *(float2*)(ob + col) = lo;
            *(float2*)(ob + (size_t)8 * D_MOD + col) = hi;
        }
    }
}

// ---------------------------------------------------------------------------
// kernel_launch
// inputs: [0]=query [1]=key [2]=value [3]=Wq [4]=Wk [5]=Wv [6]=Wo
// ---------------------------------------------------------------------------
extern "C" void kernel_launch(void* const* d_in, const int* in_sizes, int n_in,
                              void* d_out, int out_size)
{
    const float* qin = (const float*)d_in[0];
    const float* kin = (const float*)d_in[1];
    const float* vin = (const float*)d_in[2];
    const float* Wq  = (const float*)d_in[3];
    const float* Wk  = (const float*)d_in[4];
    const float* Wv  = (const float*)d_in[5];
    const float* Wo  = (const float*)d_in[6];
    float* out = (float*)d_out;

    float *dq, *dk, *dv, *dattn;
    cudaGetSymbolAddress((void**)&dq,    g_q);
    cudaGetSymbolAddress((void**)&dk,    g_k);
    cudaGetSymbolAddress((void**)&dv,    g_v);
    cudaGetSymbolAddress((void**)&dattn, g_attn);

    // raise dynamic-smem caps (host-side attribute sets; idempotent)
    cudaFuncSetAttribute(mma_gemm<3>, cudaFuncAttributeMaxDynamicSharedMemorySize,
                         GEMM_SMEM_BYTES);
    cudaFuncSetAttribute(mma_gemm<1>, cudaFuncAttributeMaxDynamicSharedMemorySize,
                         GEMM_SMEM_BYTES);
    cudaFuncSetAttribute(flash_mma, cudaFuncAttributeMaxDynamicSharedMemorySize,
                         FLASH_SMEM_BYTES);

    dim3 block(128);
    dim3 grid_qkv(D_MOD / 128, M_ROWS / 128, 3);
    dim3 grid_o(D_MOD / 128, M_ROWS / 128, 1);

    GemmTriple qkv;
    qkv.A[0] = qin; qkv.A[1] = kin; qkv.A[2] = vin;
    qkv.W[0] = Wq;  qkv.W[1] = Wk;  qkv.W[2] = Wv;
    qkv.C[0] = dq;  qkv.C[1] = dk;  qkv.C[2] = dv;
    qkv.alpha[0] = 0.125f;
    qkv.alpha[1] = 1.f;
    qkv.alpha[2] = 1.f;
    mma_gemm<3><<<grid_qkv, block, GEMM_SMEM_BYTES>>>(qkv, M_ROWS, D_MOD, D_MOD);

    dim3 agrid(L_SEQ / 128, B_SZ * NH);
    flash_mma<<<agrid, 128, FLASH_SMEM_BYTES>>>(dq, dk, dv, dattn);

    GemmTriple og;
    og.A[0] = dattn; og.W[0] = Wo; og.C[0] = out; og.alpha[0] = 1.f;
    og.A[1] = og.A[2] = nullptr; og.W[1] = og.W[2] = nullptr;
    og.C[1] = og.C[2] = nullptr; og.alpha[1] = og.alpha[2] = 0.f;
    mma_gemm<1><<<grid_o, block, GEMM_SMEM_BYTES>>>(og, M_ROWS, D_MOD, D_MOD);
}

// round 10
// speedup vs baseline: 1.4216x; 1.0476x over previous
#include <cuda_runtime.h>
#include <math_constants.h>
#include <cstdint>

// Problem constants
#define B_SZ   2
#define L_SEQ  2048
#define D_MOD  1024
#define NH     16
#define HD     64
#define M_ROWS (B_SZ * L_SEQ)   // 4096

// Scratch (allocation-free rule: __device__ globals)
__device__ float g_q[M_ROWS * D_MOD];
__device__ float g_k[M_ROWS * D_MOD];
__device__ float g_v[M_ROWS * D_MOD];
__device__ float g_attn[M_ROWS * D_MOD];

// ---------------------------------------------------------------------------
// tf32 helpers
// ---------------------------------------------------------------------------
__device__ __forceinline__ float tf32r(float x) {
    uint32_t u;
    asm("cvt.rna.tf32.f32 %0, %1;" : "=r"(u) : "f"(x));
    return __uint_as_float(u);
}

__device__ __forceinline__ void mma_tf32(float c[4],
                                         float a0, float a1, float a2, float a3,
                                         float b0, float b1)
{
    asm volatile(
        "mma.sync.aligned.m16n8k8.row.col.f32.tf32.tf32.f32 "
        "{%0,%1,%2,%3},{%4,%5,%6,%7},{%8,%9},{%0,%1,%2,%3};"
        : "+f"(c[0]), "+f"(c[1]), "+f"(c[2]), "+f"(c[3])
        : "r"(__float_as_uint(a0)), "r"(__float_as_uint(a1)),
          "r"(__float_as_uint(a2)), "r"(__float_as_uint(a3)),
          "r"(__float_as_uint(b0)), "r"(__float_as_uint(b1)));
}

__device__ __forceinline__ void cp_async16(uint32_t saddr, const void* gptr) {
    asm volatile("cp.async.cg.shared.global [%0], [%1], 16;"
                 :: "r"(saddr), "l"(gptr) : "memory");
}

// ---------------------------------------------------------------------------
// tf32 tensor-core GEMM (R8 winner): cp.async double-buffered, BK=32,
// 64x64 warp tiles. NZ==3 (QKV): output stored tf32-ROUNDED so the flash
// kernel can consume raw values with zero cvts (numerically identical to
// read-side rounding). NZ==1 (O-proj): plain fp32 output.
// ---------------------------------------------------------------------------
struct GemmTriple {
    const float* A[3];
    const float* W[3];
    float*       C[3];
    float        alpha[3];
};

#define BKG   32
#define ASTR  36
#define WSTR  136
#define A_BUF (128 * ASTR)
#define W_BUF (BKG * WSTR)
#define GEMM_SMEM_BYTES ((2 * A_BUF + 2 * W_BUF) * (int)sizeof(float))

template <int NZ>
__global__ void __launch_bounds__(128)
mma_gemm(GemmTriple args, int M, int Nc, int K)
{
    extern __shared__ float gsm[];
    const uint32_t sbase = (uint32_t)__cvta_generic_to_shared(gsm);

    const int z = (NZ > 1) ? blockIdx.z : 0;
    const float* __restrict__ A = args.A[z];
    const float* __restrict__ W = args.W[z];
    float* __restrict__ C = args.C[z];
    const float alpha = args.alpha[z];

    const int tid  = threadIdx.x;
    const int lane = tid & 31;
    const int w    = tid >> 5;
    const int g    = lane >> 2;
    const int tig  = lane & 3;
    const int mbase = (w >> 1) * 64;
    const int nbase = (w & 1) * 64;
    const int bx = blockIdx.x, by = blockIdx.y;

    const float* Abase = A + (size_t)(by * 128) * K;
    const float* Wbase = W + bx * 128;

    float acc[4][8][4];
#pragma unroll
    for (int mt = 0; mt < 4; ++mt)
#pragma unroll
        for (int nt = 0; nt < 8; ++nt)
#pragma unroll
            for (int i = 0; i < 4; ++i) acc[mt][nt][i] = 0.f;

    auto issue = [&](int k0, int b) {
        const uint32_t abuf = sbase + (uint32_t)(b * A_BUF) * 4u;
        const uint32_t wbuf = sbase + (uint32_t)(2 * A_BUF + b * W_BUF) * 4u;
#pragma unroll
        for (int i = 0; i < 8; ++i) {
            const int a = tid + i * 128;
            const int r = a >> 3, c4 = a & 7;
            cp_async16(abuf + (uint32_t)(r * ASTR + c4 * 4) * 4u,
                       Abase + (size_t)r * K + k0 + c4 * 4);
            const int krow = a >> 5, c = (a & 31) * 4;
            cp_async16(wbuf + (uint32_t)(krow * WSTR + c) * 4u,
                       Wbase + (size_t)(k0 + krow) * Nc + c);
        }
        asm volatile("cp.async.commit_group;" ::: "memory");
    };

    const int NST = K / BKG;
    issue(0, 0);
    issue(BKG, 1);

    int buf = 0;
    for (int s = 0; s < NST; ++s, buf ^= 1) {
        if (s + 1 < NST)
            asm volatile("cp.async.wait_group 1;" ::: "memory");
        else
            asm volatile("cp.async.wait_group 0;" ::: "memory");
        __syncthreads();

        const float* Ab = gsm + buf * A_BUF;
        const float* Wb = gsm + 2 * A_BUF + buf * W_BUF;
#pragma unroll
        for (int ks = 0; ks < 4; ++ks) {
            const int kr = ks * 8 + tig;
            float af[4][4], bf[8][2];
#pragma unroll
            for (int mt = 0; mt < 4; ++mt) {
                const int m = mbase + mt * 16 + g;
                af[mt][0] = tf32r(Ab[m * ASTR + kr]);
                af[mt][1] = tf32r(Ab[(m + 8) * ASTR + kr]);
                af[mt][2] = tf32r(Ab[m * ASTR + kr + 4]);
                af[mt][3] = tf32r(Ab[(m + 8) * ASTR + kr + 4]);
            }
#pragma unroll
            for (int nt = 0; nt < 8; ++nt) {
                const int n = nbase + nt * 8 + g;
                bf[nt][0] = tf32r(Wb[kr * WSTR + n]);
                bf[nt][1] = tf32r(Wb[(kr + 4) * WSTR + n]);
            }
#pragma unroll
            for (int mt = 0; mt < 4; ++mt)
#pragma unroll
                for (int nt = 0; nt < 8; ++nt)
                    mma_tf32(acc[mt][nt], af[mt][0], af[mt][1], af[mt][2], af[mt][3],
                             bf[nt][0], bf[nt][1]);
        }
        __syncthreads();
        if (s + 2 < NST) issue((s + 2) * BKG, buf);
    }

#pragma unroll
    for (int mt = 0; mt < 4; ++mt) {
        const int row0 = by * 128 + mbase + mt * 16 + g;
#pragma unroll
        for (int nt = 0; nt < 8; ++nt) {
            const int col = bx * 128 + nbase + nt * 8 + tig * 2;
            float v0 = acc[mt][nt][0] * alpha, v1 = acc[mt][nt][1] * alpha;
            float v2 = acc[mt][nt][2] * alpha, v3 = acc[mt][nt][3] * alpha;
            if (NZ == 3) {  // QKV path: pre-round for the flash kernel
                v0 = tf32r(v0); v1 = tf32r(v1); v2 = tf32r(v2); v3 = tf32r(v3);
            }
            *(float2*)(C + (size_t)row0 * Nc + col) = make_float2(v0, v1);
            *(float2*)(C + (size_t)(row0 + 8) * Nc + col) = make_float2(v2, v3);
        }
    }
}

// ---------------------------------------------------------------------------
// Flash attention v4: 4 warps x 32 q-rows, cp.async double-buffered K/V,
// separate P buffer (no K alias -> one fewer block barrier per tile),
// q/k/v arrive pre-tf32-rounded (zero cvts on the Q/K/V paths).
// grid: (L/128, B*NH), block 128.
// smem (floats): Kb[2][64*68] @0, Vb[2][64*72] @8704, Pb[128*68] @17920.
// ---------------------------------------------------------------------------
#define KS_STRIDE 68
#define VS_STRIDE 72
#define KB_OFF 0
#define VB_OFF (2 * 64 * KS_STRIDE)                 // 8704
#define PB_OFF (VB_OFF + 2 * 64 * VS_STRIDE)        // 17920
#define FLASH_SMEM_FLOATS (PB_OFF + 128 * KS_STRIDE)
#define FLASH_SMEM_BYTES  (FLASH_SMEM_FLOATS * (int)sizeof(float))

__global__ void __launch_bounds__(128, 2)
flash_mma(const float* __restrict__ q, const float* __restrict__ k,
          const float* __restrict__ v, float* __restrict__ o)
{
    extern __shared__ float fsm[];
    const uint32_t sbase = (uint32_t)__cvta_generic_to_shared(fsm);
    float* Pb = fsm + PB_OFF;

    const int tid  = threadIdx.x;
    const int lane = tid & 31;
    const int w    = tid >> 5;
    const int g    = lane >> 2;
    const int tig  = lane & 3;

    const int bn = blockIdx.y;
    const int b  = bn >> 4;
    const int n  = bn & 15;
    const int f0 = blockIdx.x * 128;

    const float* kbase = k + (size_t)b * L_SEQ * D_MOD + (size_t)n * HD;
    const float* vbase = v + (size_t)b * L_SEQ * D_MOD + (size_t)n * HD;

    const int pr0 = 32 * w + g;
    const int pr1 = 32 * w + 16 + g;

    // ---- Q fragments straight from gmem (pre-rounded, no cvt)
    float qa[2][8][4];
    {
        const float* q00 = q + (size_t)(b * L_SEQ + f0 + pr0) * D_MOD + n * HD;
        const float* q01 = q00 + (size_t)8 * D_MOD;
        const float* q10 = q + (size_t)(b * L_SEQ + f0 + pr1) * D_MOD + n * HD;
        const float* q11 = q10 + (size_t)8 * D_MOD;
#pragma unroll
        for (int ks = 0; ks < 8; ++ks) {
            const int c = ks * 8 + tig;
            qa[0][ks][0] = q00[c];
            qa[0][ks][1] = q01[c];
            qa[0][ks][2] = q00[c + 4];
            qa[0][ks][3] = q01[c + 4];
            qa[1][ks][0] = q10[c];
            qa[1][ks][1] = q11[c];
            qa[1][ks][2] = q10[c + 4];
            qa[1][ks][3] = q11[c + 4];
        }
    }

    // cp.async issue for one 64-key tile (K + V), one commit group
    auto issue_kv = [&](int t0, int bufi) {
        const uint32_t kb = sbase + (uint32_t)(KB_OFF + bufi * 64 * KS_STRIDE) * 4u;
        const uint32_t vb = sbase + (uint32_t)(VB_OFF + bufi * 64 * VS_STRIDE) * 4u;
#pragma unroll
        for (int i = 0; i < 8; ++i) {
            const int a = tid + i * 128;               // 0..1023
            const int r = a >> 4, c4 = a & 15;         // row, 16B-chunk
            cp_async16(kb + (uint32_t)(r * KS_STRIDE + c4 * 4) * 4u,
                       kbase + (size_t)(t0 + r) * D_MOD + c4 * 4);
            cp_async16(vb + (uint32_t)(r * VS_STRIDE + c4 * 4) * 4u,
                       vbase + (size_t)(t0 + r) * D_MOD + c4 * 4);
        }
        asm volatile("cp.async.commit_group;" ::: "memory");
    };

    float oacc[2][8][4];
#pragma unroll
    for (int mt = 0; mt < 2; ++mt)
#pragma unroll
        for (int nt = 0; nt < 8; ++nt)
#pragma unroll
            for (int i = 0; i < 4; ++i) oacc[mt][nt][i] = 0.f;
    float mrow[2][2] = {{-CUDART_INF_F, -CUDART_INF_F}, {-CUDART_INF_F, -CUDART_INF_F}};
    float lrow[2][2] = {{0.f, 0.f}, {0.f, 0.f}};

    const int NST = L_SEQ / 64;
    issue_kv(0, 0);
    issue_kv(64, 1);

    for (int s = 0; s < NST; ++s) {
        const int bufi = s & 1;
        if (s + 1 < NST)
            asm volatile("cp.async.wait_group 1;" ::: "memory");
        else
            asm volatile("cp.async.wait_group 0;" ::: "memory");
        __syncthreads();

        const float* Kb = fsm + KB_OFF + bufi * 64 * KS_STRIDE;
        const float* Vb = fsm + VB_OFF + bufi * 64 * VS_STRIDE;

        // ---- S = Q @ K^T (no cvt: K pre-rounded)
        float sacc[2][8][4];
#pragma unroll
        for (int mt = 0; mt < 2; ++mt)
#pragma unroll
            for (int nt = 0; nt < 8; ++nt)
#pragma unroll
                for (int i = 0; i < 4; ++i) sacc[mt][nt][i] = 0.f;
#pragma unroll
        for (int nt = 0; nt < 8; ++nt) {
            const int trow = nt * 8 + g;
#pragma unroll
            for (int ks = 0; ks < 8; ++ks) {
                const float b0 = Kb[trow * KS_STRIDE + ks * 8 + tig];
                const float b1 = Kb[trow * KS_STRIDE + ks * 8 + tig + 4];
                mma_tf32(sacc[0][nt], qa[0][ks][0], qa[0][ks][1], qa[0][ks][2], qa[0][ks][3], b0, b1);
                mma_tf32(sacc[1][nt], qa[1][ks][0], qa[1][ks][1], qa[1][ks][2], qa[1][ks][3], b0, b1);
            }
        }
        // P buffer is separate; no block barrier needed before softmax.

        // ---- online softmax, write P (warp-private rows)
#pragma unroll
        for (int mt = 0; mt < 2; ++mt) {
            const int pr = (mt == 0) ? pr0 : pr1;
            float tm0 = -CUDART_INF_F, tm1 = -CUDART_INF_F;
#pragma unroll
            for (int nt = 0; nt < 8; ++nt) {
                tm0 = fmaxf(tm0, fmaxf(sacc[mt][nt][0], sacc[mt][nt][1]));
                tm1 = fmaxf(tm1, fmaxf(sacc[mt][nt][2], sacc[mt][nt][3]));
            }
            tm0 = fmaxf(tm0, __shfl_xor_sync(0xffffffffu, tm0, 1));
            tm0 = fmaxf(tm0, __shfl_xor_sync(0xffffffffu, tm0, 2));
            tm1 = fmaxf(tm1, __shfl_xor_sync(0xffffffffu, tm1, 1));
            tm1 = fmaxf(tm1, __shfl_xor_sync(0xffffffffu, tm1, 2));

            const float nm0 = fmaxf(mrow[mt][0], tm0);
            const float nm1 = fmaxf(mrow[mt][1], tm1);
            const float sc0 = __expf(mrow[mt][0] - nm0);
            const float sc1 = __expf(mrow[mt][1] - nm1);
            mrow[mt][0] = nm0; mrow[mt][1] = nm1;
            lrow[mt][0] *= sc0; lrow[mt][1] *= sc1;
#pragma unroll
            for (int nt = 0; nt < 8; ++nt) {
                oacc[mt][nt][0] *= sc0; oacc[mt][nt][1] *= sc0;
                oacc[mt][nt][2] *= sc1; oacc[mt][nt][3] *= sc1;
            }

            float rs0 = 0.f, rs1 = 0.f;
#pragma unroll
            for (int nt = 0; nt < 8; ++nt) {
                const float p0 = __expf(sacc[mt][nt][0] - nm0);
                const float p1 = __expf(sacc[mt][nt][1] - nm0);
                const float p2 = __expf(sacc[mt][nt][2] - nm1);
                const float p3 = __expf(sacc[mt][nt][3] - nm1);
                rs0 += p0 + p1;  rs1 += p2 + p3;
                const int col = nt * 8 + tig * 2;
                Pb[pr * KS_STRIDE + col]           = tf32r(p0);
                Pb[pr * KS_STRIDE + col + 1]       = tf32r(p1);
                Pb[(pr + 8) * KS_STRIDE + col]     = tf32r(p2);
                Pb[(pr + 8) * KS_STRIDE + col + 1] = tf32r(p3);
            }
            rs0 += __shfl_xor_sync(0xffffffffu, rs0, 1);
            rs0 += __shfl_xor_sync(0xffffffffu, rs0, 2);
            rs1 += __shfl_xor_sync(0xffffffffu, rs1, 1);
            rs1 += __shfl_xor_sync(0xffffffffu, rs1, 2);
            lrow[mt][0] += rs0; lrow[mt][1] += rs1;
        }
        __syncwarp();

        // ---- O += P @ V (no cvt: V pre-rounded)
#pragma unroll
        for (int kt = 0; kt < 8; ++kt) {
            const int c = kt * 8 + tig;
            const float a00 = Pb[pr0 * KS_STRIDE + c];
            const float a01 = Pb[(pr0 + 8) * KS_STRIDE + c];
            const float a02 = Pb[pr0 * KS_STRIDE + c + 4];
            const float a03 = Pb[(pr0 + 8) * KS_STRIDE + c + 4];
            const float a10 = Pb[pr1 * KS_STRIDE + c];
            const float a11 = Pb[(pr1 + 8) * KS_STRIDE + c];
            const float a12 = Pb[pr1 * KS_STRIDE + c + 4];
            const float a13 = Pb[(pr1 + 8) * KS_STRIDE + c + 4];
#pragma unroll
            for (int nt = 0; nt < 8; ++nt) {
                const float b0 = Vb[(kt * 8 + tig) * VS_STRIDE + nt * 8 + g];
                const float b1 = Vb[(kt * 8 + tig + 4) * VS_STRIDE + nt * 8 + g];
                mma_tf32(oacc[0][nt], a00, a01, a02, a03, b0, b1);
                mma_tf32(oacc[1][nt], a10, a11, a12, a13, b0, b1);
            }
        }
        __syncthreads();   // all warps done with K/V[bufi] before refill
        if (s + 2 < NST) issue_kv((s + 2) * 64, bufi);
    }

    // ---- epilogue
#pragma unroll
    for (int mt = 0; mt < 2; ++mt) {
        const int pr = (mt == 0) ? pr0 : pr1;
        const float inv0 = 1.f / lrow[mt][0];
        const float inv1 = 1.f / lrow[mt][1];
        float* ob = o + (size_t)(b * L_SEQ + f0 + pr) * D_MOD + (size_t)n * HD;
#pragma unroll
        for (int nt = 0; nt < 8; ++nt) {
            const int col = nt * 8 + tig * 2;
            float2 lo = make_float2(oacc[mt][nt][0] * inv0, oacc[mt][nt][1] * inv0);
            float2 hi = make_float2(oacc[mt][nt][2] * inv1, oacc[mt][nt][3] * inv1);
            *(float2*)(ob + col) = lo;
            *(float2*)(ob + (size_t)8 * D_MOD + col) = hi;
        }
    }
}

// ---------------------------------------------------------------------------
// kernel_launch
// inputs: [0]=query [1]=key [2]=value [3]=Wq [4]=Wk [5]=Wv [6]=Wo
// ---------------------------------------------------------------------------
extern "C" void kernel_launch(void* const* d_in, const int* in_sizes, int n_in,
                              void* d_out, int out_size)
{
    const float* qin = (const float*)d_in[0];
    const float* kin = (const float*)d_in[1];
    const float* vin = (const float*)d_in[2];
    const float* Wq  = (const float*)d_in[3];
    const float* Wk  = (const float*)d_in[4];
    const float* Wv  = (const float*)d_in[5];
    const float* Wo  = (const float*)d_in[6];
    float* out = (float*)d_out;

    float *dq, *dk, *dv, *dattn;
    cudaGetSymbolAddress((void**)&dq,    g_q);
    cudaGetSymbolAddress((void**)&dk,    g_k);
    cudaGetSymbolAddress((void**)&dv,    g_v);
    cudaGetSymbolAddress((void**)&dattn, g_attn);

    cudaFuncSetAttribute(mma_gemm<3>, cudaFuncAttributeMaxDynamicSharedMemorySize,
                         GEMM_SMEM_BYTES);
    cudaFuncSetAttribute(mma_gemm<1>, cudaFuncAttributeMaxDynamicSharedMemorySize,
                         GEMM_SMEM_BYTES);
    cudaFuncSetAttribute(flash_mma, cudaFuncAttributeMaxDynamicSharedMemorySize,
                         FLASH_SMEM_BYTES);

    dim3 block(128);
    dim3 grid_qkv(D_MOD / 128, M_ROWS / 128, 3);
    dim3 grid_o(D_MOD / 128, M_ROWS / 128, 1);

    GemmTriple qkv;
    qkv.A[0] = qin; qkv.A[1] = kin; qkv.A[2] = vin;
    qkv.W[0] = Wq;  qkv.W[1] = Wk;  qkv.W[2] = Wv;
    qkv.C[0] = dq;  qkv.C[1] = dk;  qkv.C[2] = dv;
    qkv.alpha[0] = 0.125f;
    qkv.alpha[1] = 1.f;
    qkv.alpha[2] = 1.f;
    mma_gemm<3><<<grid_qkv, block, GEMM_SMEM_BYTES>>>(qkv, M_ROWS, D_MOD, D_MOD);

    dim3 agrid(L_SEQ / 128, B_SZ * NH);
    flash_mma<<<agrid, 128, FLASH_SMEM_BYTES>>>(dq, dk, dv, dattn);

    GemmTriple og;
    og.A[0] = dattn; og.W[0] = Wo; og.C[0] = out; og.alpha[0] = 1.f;
    og.A[1] = og.A[2] = nullptr; og.W[1] = og.W[2] = nullptr;
    og.C[1] = og.C[2] = nullptr; og.alpha[1] = og.alpha[2] = 0.f;
    mma_gemm<1><<<grid_o, block, GEMM_SMEM_BYTES>>>(og, M_ROWS, D_MOD, D_MOD);
}

// round 11
// speedup vs baseline: 2.3603x; 1.6603x over previous
#include <cuda_runtime.h>
#include <cuda_fp16.h>
#include <math_constants.h>
#include <cstdint>

// Problem constants
#define B_SZ   2
#define L_SEQ  2048
#define D_MOD  1024
#define NH     16
#define HD     64
#define M_ROWS (B_SZ * L_SEQ)   // 4096

// Scratch (allocation-free rule: __device__ globals) — all fp16 now
__device__ __half g_inq[M_ROWS * D_MOD];
__device__ __half g_ink[M_ROWS * D_MOD];
__device__ __half g_inv[M_ROWS * D_MOD];
__device__ __half g_wqt[D_MOD * D_MOD];
__device__ __half g_wkt[D_MOD * D_MOD];
__device__ __half g_wvt[D_MOD * D_MOD];
__device__ __half g_wot[D_MOD * D_MOD];
__device__ __half g_qh[M_ROWS * D_MOD];
__device__ __half g_kh[M_ROWS * D_MOD];
__device__ __half g_vt[B_SZ * NH * HD * L_SEQ];   // [b*NH+n][h][t]
__device__ __half g_attnh[M_ROWS * D_MOD];

// ---------------------------------------------------------------------------
// helpers
// ---------------------------------------------------------------------------
__device__ __forceinline__ void mma_f16(float c[4],
                                        uint32_t a0, uint32_t a1, uint32_t a2, uint32_t a3,
                                        uint32_t b0, uint32_t b1)
{
    asm volatile(
        "mma.sync.aligned.m16n8k16.row.col.f32.f16.f16.f32 "
        "{%0,%1,%2,%3},{%4,%5,%6,%7},{%8,%9},{%0,%1,%2,%3};"
        : "+f"(c[0]), "+f"(c[1]), "+f"(c[2]), "+f"(c[3])
        : "r"(a0), "r"(a1), "r"(a2), "r"(a3), "r"(b0), "r"(b1));
}

__device__ __forceinline__ void cp_async16(uint32_t saddr, const void* gptr) {
    asm volatile("cp.async.cg.shared.global [%0], [%1], 16;"
                 :: "r"(saddr), "l"(gptr) : "memory");
}

// ---------------------------------------------------------------------------
// Convert kernels (one-time pre-pass)
// ---------------------------------------------------------------------------
struct CvtArgs { const float* in[3]; __half* out[3]; };

__global__ void __launch_bounds__(256)
cvt_inputs(CvtArgs a)
{
    const int z = blockIdx.z;
    const float4* in = (const float4*)a.in[z];
    __half2* out = (__half2*)a.out[z];
    const int idx = blockIdx.x * 256 + threadIdx.x;   // over float4 units
    float4 v = in[idx];
    out[2 * idx]     = __floats2half2_rn(v.x, v.y);
    out[2 * idx + 1] = __floats2half2_rn(v.z, v.w);
}

struct TpArgs { const float* in[4]; __half* out[4]; };

// fp32 [k][n] -> fp16 [n][k]
__global__ void __launch_bounds__(256)
cvt_wt(TpArgs a)
{
    __shared__ float t[32][33];
    const float* in = a.in[blockIdx.z];
    __half* out = a.out[blockIdx.z];
    const int tx = threadIdx.x, ty = threadIdx.y;
    const int x0 = blockIdx.x * 32, y0 = blockIdx.y * 32;
#pragma unroll
    for (int j = 0; j < 32; j += 8)
        t[ty + j][tx] = in[(size_t)(y0 + ty + j) * D_MOD + x0 + tx];
    __syncthreads();
#pragma unroll
    for (int j = 0; j < 32; j += 8)
        out[(size_t)(x0 + ty + j) * D_MOD + y0 + tx] = __float2half_rn(t[tx][ty + j]);
}

// ---------------------------------------------------------------------------
// fp16 tensor-core GEMM: C = alpha * A[M,K] @ Wt[Nc,K]^T.
// A, Wt fp16 row-major-in-K. CTA 128x128, BK=64, 4 warps 64x64 (m16n8k16).
// NZ==3: fp16 output (z==2 -> V written TRANSPOSED to g_vt[bh][h][t]).
// NZ==1: fp32 output.
// ---------------------------------------------------------------------------
struct HGemmArgs {
    const __half* A[3];
    const __half* Wt[3];
    void*         C[3];
    float         alpha[3];
};

#define HBK  64
#define HAS  72                      // smem row stride (halfs)
#define HA_BUF (128 * HAS)           // halfs per buffer
#define HGEMM_SMEM_BYTES (4 * HA_BUF * 2)   // A x2 + W x2, bytes (73728)

template <int NZ>
__global__ void __launch_bounds__(128)
hgemm(HGemmArgs args, int M, int Nc, int K)
{
    extern __shared__ __half hsm[];
    const uint32_t sbase = (uint32_t)__cvta_generic_to_shared(hsm);

    const int z = (NZ > 1) ? blockIdx.z : 0;
    const __half* __restrict__ A  = args.A[z];
    const __half* __restrict__ Wt = args.Wt[z];
    const float alpha = args.alpha[z];
    const bool vtr = (NZ == 3 && z == 2);

    const int tid  = threadIdx.x;
    const int lane = tid & 31;
    const int w    = tid >> 5;
    const int g    = lane >> 2;
    const int tig  = lane & 3;
    const int mbase = (w >> 1) * 64;
    const int nbase = (w & 1) * 64;
    const int bx = blockIdx.x, by = blockIdx.y;

    const __half* Abase = A + (size_t)(by * 128) * K;
    const __half* Wbase = Wt + (size_t)(bx * 128) * K;

    float acc[4][8][4];
#pragma unroll
    for (int mt = 0; mt < 4; ++mt)
#pragma unroll
        for (int nt = 0; nt < 8; ++nt)
#pragma unroll
            for (int i = 0; i < 4; ++i) acc[mt][nt][i] = 0.f;

    // per stage: A 128x64 halfs = 1024 16B-chunks, same for W; 8+8 per thread
    auto issue = [&](int k0, int b) {
        const uint32_t abuf = sbase + (uint32_t)(b * HA_BUF) * 2u;
        const uint32_t wbuf = sbase + (uint32_t)((2 + b) * HA_BUF) * 2u;
#pragma unroll
        for (int i = 0; i < 8; ++i) {
            const int a = tid + i * 128;
            const int r = a >> 3, c8 = a & 7;
            cp_async16(abuf + (uint32_t)(r * HAS + c8 * 8) * 2u,
                       Abase + (size_t)r * K + k0 + c8 * 8);
            cp_async16(wbuf + (uint32_t)(r * HAS + c8 * 8) * 2u,
                       Wbase + (size_t)r * K + k0 + c8 * 8);
        }
        asm volatile("cp.async.commit_group;" ::: "memory");
    };

    const int NST = K / HBK;   // 16
    issue(0, 0);
    issue(HBK, 1);

    int buf = 0;
    for (int s = 0; s < NST; ++s, buf ^= 1) {
        if (s + 1 < NST)
            asm volatile("cp.async.wait_group 1;" ::: "memory");
        else
            asm volatile("cp.async.wait_group 0;" ::: "memory");
        __syncthreads();

        const __half* Ab = hsm + buf * HA_BUF;
        const __half* Wb = hsm + (2 + buf) * HA_BUF;
#pragma unroll
        for (int ks = 0; ks < 4; ++ks) {            // 4 x K16
            const int kc = ks * 16 + tig * 2;
            uint32_t af[4][4], bf[8][2];
#pragma unroll
            for (int mt = 0; mt < 4; ++mt) {
                const int m = mbase + mt * 16 + g;
                af[mt][0] = *(const uint32_t*)(Ab + m * HAS + kc);
                af[mt][1] = *(const uint32_t*)(Ab + (m + 8) * HAS + kc);
                af[mt][2] = *(const uint32_t*)(Ab + m * HAS + kc + 8);
                af[mt][3] = *(const uint32_t*)(Ab + (m + 8) * HAS + kc + 8);
            }
#pragma unroll
            for (int nt = 0; nt < 8; ++nt) {
                const int n = nbase + nt * 8 + g;
                bf[nt][0] = *(const uint32_t*)(Wb + n * HAS + kc);
                bf[nt][1] = *(const uint32_t*)(Wb + n * HAS + kc + 8);
            }
#pragma unroll
            for (int mt = 0; mt < 4; ++mt)
#pragma unroll
                for (int nt = 0; nt < 8; ++nt)
                    mma_f16(acc[mt][nt], af[mt][0], af[mt][1], af[mt][2], af[mt][3],
                            bf[nt][0], bf[nt][1]);
        }
        __syncthreads();
        if (s + 2 < NST) issue((s + 2) * HBK, buf);
    }

    // epilogue
#pragma unroll
    for (int mt = 0; mt < 4; ++mt) {
        const int row0 = by * 128 + mbase + mt * 16 + g;
#pragma unroll
        for (int nt = 0; nt < 8; ++nt) {
            const int col = bx * 128 + nbase + nt * 8 + tig * 2;
            const float v0 = acc[mt][nt][0] * alpha, v1 = acc[mt][nt][1] * alpha;
            const float v2 = acc[mt][nt][2] * alpha, v3 = acc[mt][nt][3] * alpha;
            if (NZ == 1) {
                float* C = (float*)args.C[0];
                *(float2*)(C + (size_t)row0 * Nc + col) = make_float2(v0, v1);
                *(float2*)(C + (size_t)(row0 + 8) * Nc + col) = make_float2(v2, v3);
            } else if (!vtr) {
                __half* C = (__half*)args.C[z];
                *(__half2*)(C + (size_t)row0 * Nc + col) = __floats2half2_rn(v0, v1);
                *(__half2*)(C + (size_t)(row0 + 8) * Nc + col) = __floats2half2_rn(v2, v3);
            } else {
                // V: write transposed g_vt[(b*NH+nh)*HD + h][t]
                __half* C = (__half*)args.C[2];
                const int nh = col >> 6, h = col & 63;
                const int b0 = row0 >> 11, t0 = row0 & 2047;
                const size_t base0 = ((size_t)(b0 * NH + nh) * HD + h) * L_SEQ + t0;
                C[base0]             = __float2half_rn(v0);
                C[base0 + L_SEQ]     = __float2half_rn(v1);   // h+1
                C[base0 + 8]         = __float2half_rn(v2);   // t+8
                C[base0 + L_SEQ + 8] = __float2half_rn(v3);
            }
        }
    }
}

// ---------------------------------------------------------------------------
// fp16 flash attention: 4 warps x 32 q-rows, cp.async double-buffered K/V^T,
// separate fp16 P buffer. grid (L/128, B*NH), block 128.
// smem (halfs): Kb[2][64*72] @0, Vt[2][64*72] @9216, Pb[128*72] @18432.
// ---------------------------------------------------------------------------
#define FKH 72
#define FKB_OFF 0
#define FVB_OFF (2 * 64 * FKH)              // 9216
#define FPB_OFF (FVB_OFF + 2 * 64 * FKH)    // 18432
#define FLASH_SMEM_BYTES ((FPB_OFF + 128 * FKH) * 2)   // 55296

__global__ void __launch_bounds__(128, 2)
flash_h(const __half* __restrict__ q, const __half* __restrict__ k,
        const __half* __restrict__ vt, __half* __restrict__ o)
{
    extern __shared__ __half hsm[];
    const uint32_t sbase = (uint32_t)__cvta_generic_to_shared(hsm);
    __half* Pb = hsm + FPB_OFF;

    const int tid  = threadIdx.x;
    const int lane = tid & 31;
    const int w    = tid >> 5;
    const int g    = lane >> 2;
    const int tig  = lane & 3;

    const int bn = blockIdx.y;
    const int b  = bn >> 4;
    const int n  = bn & 15;
    const int f0 = blockIdx.x * 128;

    const __half* kbase  = k + (size_t)(b * L_SEQ) * D_MOD + n * HD;
    const __half* vtbase = vt + (size_t)(b * NH + n) * HD * L_SEQ;

    const int pr0 = 32 * w + g;
    const int pr1 = 32 * w + 16 + g;

    // ---- Q fragments from gmem (fp16, one-time)
    uint32_t qa[2][4][4];
    {
        const __half* q00 = q + (size_t)(b * L_SEQ + f0 + pr0) * D_MOD + n * HD;
        const __half* q01 = q00 + (size_t)8 * D_MOD;
        const __half* q10 = q + (size_t)(b * L_SEQ + f0 + pr1) * D_MOD + n * HD;
        const __half* q11 = q10 + (size_t)8 * D_MOD;
#pragma unroll
        for (int ks = 0; ks < 4; ++ks) {
            const int kc = ks * 16 + tig * 2;
            qa[0][ks][0] = *(const uint32_t*)(q00 + kc);
            qa[0][ks][1] = *(const uint32_t*)(q01 + kc);
            qa[0][ks][2] = *(const uint32_t*)(q00 + kc + 8);
            qa[0][ks][3] = *(const uint32_t*)(q01 + kc + 8);
            qa[1][ks][0] = *(const uint32_t*)(q10 + kc);
            qa[1][ks][1] = *(const uint32_t*)(q11 + kc);
            qa[1][ks][2] = *(const uint32_t*)(q10 + kc + 8);
            qa[1][ks][3] = *(const uint32_t*)(q11 + kc + 8);
        }
    }

    // cp.async one 64-key tile: K [t][h] and V^T [h][t], 4+4 chunks per thread
    auto issue_kv = [&](int t0, int bufi) {
        const uint32_t kb = sbase + (uint32_t)(FKB_OFF + bufi * 64 * FKH) * 2u;
        const uint32_t vb = sbase + (uint32_t)(FVB_OFF + bufi * 64 * FKH) * 2u;
#pragma unroll
        for (int i = 0; i < 4; ++i) {
            const int a = tid + i * 128;          // 0..511
            const int r = a >> 3, c8 = a & 7;
            cp_async16(kb + (uint32_t)(r * FKH + c8 * 8) * 2u,
                       kbase + (size_t)(t0 + r) * D_MOD + c8 * 8);
            cp_async16(vb + (uint32_t)(r * FKH + c8 * 8) * 2u,
                       vtbase + (size_t)r * L_SEQ + t0 + c8 * 8);
        }
        asm volatile("cp.async.commit_group;" ::: "memory");
    };

    float oacc[2][8][4];
#pragma unroll
    for (int mt = 0; mt < 2; ++mt)
#pragma unroll
        for (int nt = 0; nt < 8; ++nt)
#pragma unroll
            for (int i = 0; i < 4; ++i) oacc[mt][nt][i] = 0.f;
    float mrow[2][2] = {{-CUDART_INF_F, -CUDART_INF_F}, {-CUDART_INF_F, -CUDART_INF_F}};
    float lrow[2][2] = {{0.f, 0.f}, {0.f, 0.f}};

    const int NST = L_SEQ / 64;
    issue_kv(0, 0);
    issue_kv(64, 1);

    for (int s = 0; s < NST; ++s) {
        const int bufi = s & 1;
        if (s + 1 < NST)
            asm volatile("cp.async.wait_group 1;" ::: "memory");
        else
            asm volatile("cp.async.wait_group 0;" ::: "memory");
        __syncthreads();

        const __half* Kb = hsm + FKB_OFF + bufi * 64 * FKH;
        const __half* Vt = hsm + FVB_OFF + bufi * 64 * FKH;

        // ---- S = Q @ K^T
        float sacc[2][8][4];
#pragma unroll
        for (int mt = 0; mt < 2; ++mt)
#pragma unroll
            for (int nt = 0; nt < 8; ++nt)
#pragma unroll
                for (int i = 0; i < 4; ++i) sacc[mt][nt][i] = 0.f;
#pragma unroll
        for (int nt = 0; nt < 8; ++nt) {
            const int trow = nt * 8 + g;
#pragma unroll
            for (int ks = 0; ks < 4; ++ks) {
                const int kc = ks * 16 + tig * 2;
                const uint32_t b0 = *(const uint32_t*)(Kb + trow * FKH + kc);
                const uint32_t b1 = *(const uint32_t*)(Kb + trow * FKH + kc + 8);
                mma_f16(sacc[0][nt], qa[0][ks][0], qa[0][ks][1], qa[0][ks][2], qa[0][ks][3], b0, b1);
                mma_f16(sacc[1][nt], qa[1][ks][0], qa[1][ks][1], qa[1][ks][2], qa[1][ks][3], b0, b1);
            }
        }

        // ---- online softmax, P -> fp16 smem (warp-private rows)
#pragma unroll
        for (int mt = 0; mt < 2; ++mt) {
            const int pr = (mt == 0) ? pr0 : pr1;
            float tm0 = -CUDART_INF_F, tm1 = -CUDART_INF_F;
#pragma unroll
            for (int nt = 0; nt < 8; ++nt) {
                tm0 = fmaxf(tm0, fmaxf(sacc[mt][nt][0], sacc[mt][nt][1]));
                tm1 = fmaxf(tm1, fmaxf(sacc[mt][nt][2], sacc[mt][nt][3]));
            }
            tm0 = fmaxf(tm0, __shfl_xor_sync(0xffffffffu, tm0, 1));
            tm0 = fmaxf(tm0, __shfl_xor_sync(0xffffffffu, tm0, 2));
            tm1 = fmaxf(tm1, __shfl_xor_sync(0xffffffffu, tm1, 1));
            tm1 = fmaxf(tm1, __shfl_xor_sync(0xffffffffu, tm1, 2));

            const float nm0 = fmaxf(mrow[mt][0], tm0);
            const float nm1 = fmaxf(mrow[mt][1], tm1);
            const float sc0 = __expf(mrow[mt][0] - nm0);
            const float sc1 = __expf(mrow[mt][1] - nm1);
            mrow[mt][0] = nm0; mrow[mt][1] = nm1;
            lrow[mt][0] *= sc0; lrow[mt][1] *= sc1;
#pragma unroll
            for (int nt = 0; nt < 8; ++nt) {
                oacc[mt][nt][0] *= sc0; oacc[mt][nt][1] *= sc0;
                oacc[mt][nt][2] *= sc1; oacc[mt][nt][3] *= sc1;
            }

            float rs0 = 0.f, rs1 = 0.f;
#pragma unroll
            for (int nt = 0; nt < 8; ++nt) {
                const float p0 = __expf(sacc[mt][nt][0] - nm0);
                const float p1 = __expf(sacc[mt][nt][1] - nm0);
                const float p2 = __expf(sacc[mt][nt][2] - nm1);
                const float p3 = __expf(sacc[mt][nt][3] - nm1);
                rs0 += p0 + p1;  rs1 += p2 + p3;
                const int col = nt * 8 + tig * 2;
                *(__half2*)(Pb + pr * FKH + col)       = __floats2half2_rn(p0, p1);
                *(__half2*)(Pb + (pr + 8) * FKH + col) = __floats2half2_rn(p2, p3);
            }
            rs0 += __shfl_xor_sync(0xffffffffu, rs0, 1);
            rs0 += __shfl_xor_sync(0xffffffffu, rs0, 2);
            rs1 += __shfl_xor_sync(0xffffffffu, rs1, 1);
            rs1 += __shfl_xor_sync(0xffffffffu, rs1, 2);
            lrow[mt][0] += rs0; lrow[mt][1] += rs1;
        }
        __syncwarp();

        // ---- O += P @ V  (B from V^T, pairs along t)
#pragma unroll
        for (int kt = 0; kt < 4; ++kt) {
            const int kc = kt * 16 + tig * 2;
            const uint32_t a00 = *(const uint32_t*)(Pb + pr0 * FKH + kc);
            const uint32_t a01 = *(const uint32_t*)(Pb + (pr0 + 8) * FKH + kc);
            const uint32_t a02 = *(const uint32_t*)(Pb + pr0 * FKH + kc + 8);
            const uint32_t a03 = *(const uint32_t*)(Pb + (pr0 + 8) * FKH + kc + 8);
            const uint32_t a10 = *(const uint32_t*)(Pb + pr1 * FKH + kc);
            const uint32_t a11 = *(const uint32_t*)(Pb + (pr1 + 8) * FKH + kc);
            const uint32_t a12 = *(const uint32_t*)(Pb + pr1 * FKH + kc + 8);
            const uint32_t a13 = *(const uint32_t*)(Pb + (pr1 + 8) * FKH + kc + 8);
#pragma unroll
            for (int nt = 0; nt < 8; ++nt) {
                const int hrow = nt * 8 + g;
                const uint32_t b0 = *(const uint32_t*)(Vt + hrow * FKH + kc);
                const uint32_t b1 = *(const uint32_t*)(Vt + hrow * FKH + kc + 8);
                mma_f16(oacc[0][nt], a00, a01, a02, a03, b0, b1);
                mma_f16(oacc[1][nt], a10, a11, a12, a13, b0, b1);
            }
        }
        __syncthreads();
        if (s + 2 < NST) issue_kv((s + 2) * 64, bufi);
    }

    // ---- epilogue: attn -> fp16 gmem
#pragma unroll
    for (int mt = 0; mt < 2; ++mt) {
        const int pr = (mt == 0) ? pr0 : pr1;
        const float inv0 = 1.f / lrow[mt][0];
        const float inv1 = 1.f / lrow[mt][1];
        __half* ob = o + (size_t)(b * L_SEQ + f0 + pr) * D_MOD + n * HD;
#pragma unroll
        for (int nt = 0; nt < 8; ++nt) {
            const int col = nt * 8 + tig * 2;
            *(__half2*)(ob + col) = __floats2half2_rn(oacc[mt][nt][0] * inv0,
                                                      oacc[mt][nt][1] * inv0);
            *(__half2*)(ob + (size_t)8 * D_MOD + col) = __floats2half2_rn(oacc[mt][nt][2] * inv1,
                                                                          oacc[mt][nt][3] * inv1);
        }
    }
}

// ---------------------------------------------------------------------------
// kernel_launch
// inputs: [0]=query [1]=key [2]=value [3]=Wq [4]=Wk [5]=Wv [6]=Wo
// ---------------------------------------------------------------------------
extern "C" void kernel_launch(void* const* d_in, const int* in_sizes, int n_in,
                              void* d_out, int out_size)
{
    const float* qin = (const float*)d_in[0];
    const float* kin = (const float*)d_in[1];
    const float* vin = (const float*)d_in[2];
    const float* Wq  = (const float*)d_in[3];
    const float* Wk  = (const float*)d_in[4];
    const float* Wv  = (const float*)d_in[5];
    const float* Wo  = (const float*)d_in[6];
    float* out = (float*)d_out;

    __half *inq, *ink, *inv, *wqt, *wkt, *wvt, *wot, *qh, *kh, *vt, *attnh;
    cudaGetSymbolAddress((void**)&inq,   g_inq);
    cudaGetSymbolAddress((void**)&ink,   g_ink);
    cudaGetSymbolAddress((void**)&inv,   g_inv);
    cudaGetSymbolAddress((void**)&wqt,   g_wqt);
    cudaGetSymbolAddress((void**)&wkt,   g_wkt);
    cudaGetSymbolAddress((void**)&wvt,   g_wvt);
    cudaGetSymbolAddress((void**)&wot,   g_wot);
    cudaGetSymbolAddress((void**)&qh,    g_qh);
    cudaGetSymbolAddress((void**)&kh,    g_kh);
    cudaGetSymbolAddress((void**)&vt,    g_vt);
    cudaGetSymbolAddress((void**)&attnh, g_attnh);

    cudaFuncSetAttribute(hgemm<3>, cudaFuncAttributeMaxDynamicSharedMemorySize,
                         HGEMM_SMEM_BYTES);
    cudaFuncSetAttribute(hgemm<1>, cudaFuncAttributeMaxDynamicSharedMemorySize,
                         HGEMM_SMEM_BYTES);
    cudaFuncSetAttribute(flash_h, cudaFuncAttributeMaxDynamicSharedMemorySize,
                         FLASH_SMEM_BYTES);

    // 0) convert inputs + weights (transposed) to fp16
    CvtArgs ca;
    ca.in[0] = qin; ca.in[1] = kin; ca.in[2] = vin;
    ca.out[0] = inq; ca.out[1] = ink; ca.out[2] = inv;
    cvt_inputs<<<dim3(M_ROWS * D_MOD / 4 / 256, 1, 3), 256>>>(ca);

    TpArgs ta;
    ta.in[0] = Wq; ta.in[1] = Wk; ta.in[2] = Wv; ta.in[3] = Wo;
    ta.out[0] = wqt; ta.out[1] = wkt; ta.out[2] = wvt; ta.out[3] = wot;
    cvt_wt<<<dim3(32, 32, 4), dim3(32, 8)>>>(ta);

    // 1) QKV projections (fp16 mma; q scaled; V written transposed)
    HGemmArgs qkv;
    qkv.A[0] = inq; qkv.A[1] = ink; qkv.A[2] = inv;
    qkv.Wt[0] = wqt; qkv.Wt[1] = wkt; qkv.Wt[2] = wvt;
    qkv.C[0] = qh;  qkv.C[1] = kh;  qkv.C[2] = vt;
    qkv.alpha[0] = 0.125f;
    qkv.alpha[1] = 1.f;
    qkv.alpha[2] = 1.f;
    hgemm<3><<<dim3(D_MOD / 128, M_ROWS / 128, 3), 128, HGEMM_SMEM_BYTES>>>(
        qkv, M_ROWS, D_MOD, D_MOD);

    // 2) fp16 flash attention
    flash_h<<<dim3(L_SEQ / 128, B_SZ * NH), 128, FLASH_SMEM_BYTES>>>(qh, kh, vt, attnh);

    // 3) output projection (fp16 in, fp32 out)
    HGemmArgs og;
    og.A[0] = attnh; og.Wt[0] = wot; og.C[0] = out; og.alpha[0] = 1.f;
    og.A[1] = og.A[2] = nullptr; og.Wt[1] = og.Wt[2] = nullptr;
    og.C[1] = og.C[2] = nullptr; og.alpha[1] = og.alpha[2] = 0.f;
    hgemm<1><<<dim3(D_MOD / 128, M_ROWS / 128, 1), 128, HGEMM_SMEM_BYTES>>>(
        og, M_ROWS, D_MOD, D_MOD);
}

// round 12
// speedup vs baseline: 2.4666x; 1.0450x over previous
#include <cuda_runtime.h>
#include <cuda_fp16.h>
#include <math_constants.h>
#include <cstdint>

// Problem constants
#define B_SZ   2
#define L_SEQ  2048
#define D_MOD  1024
#define NH     16
#define HD     64
#define M_ROWS (B_SZ * L_SEQ)   // 4096

// Scratch (allocation-free rule: __device__ globals) — fp16 pipeline
__device__ __half g_inq[M_ROWS * D_MOD];
__device__ __half g_ink[M_ROWS * D_MOD];
__device__ __half g_inv[M_ROWS * D_MOD];
__device__ __half g_wqt[D_MOD * D_MOD];
__device__ __half g_wkt[D_MOD * D_MOD];
__device__ __half g_wvt[D_MOD * D_MOD];
__device__ __half g_wot[D_MOD * D_MOD];
__device__ __half g_qh[M_ROWS * D_MOD];
__device__ __half g_kh[M_ROWS * D_MOD];
__device__ __half g_vt[B_SZ * NH * HD * L_SEQ];   // [b*NH+n][h][t]
__device__ __half g_attnh[M_ROWS * D_MOD];

// ---------------------------------------------------------------------------
// helpers
// ---------------------------------------------------------------------------
__device__ __forceinline__ void mma_f16(float c[4],
                                        uint32_t a0, uint32_t a1, uint32_t a2, uint32_t a3,
                                        uint32_t b0, uint32_t b1)
{
    asm volatile(
        "mma.sync.aligned.m16n8k16.row.col.f32.f16.f16.f32 "
        "{%0,%1,%2,%3},{%4,%5,%6,%7},{%8,%9},{%0,%1,%2,%3};"
        : "+f"(c[0]), "+f"(c[1]), "+f"(c[2]), "+f"(c[3])
        : "r"(a0), "r"(a1), "r"(a2), "r"(a3), "r"(b0), "r"(b1));
}

__device__ __forceinline__ void cp_async16(uint32_t saddr, const void* gptr) {
    asm volatile("cp.async.cg.shared.global [%0], [%1], 16;"
                 :: "r"(saddr), "l"(gptr) : "memory");
}

__device__ __forceinline__ void ldsm_x4(uint32_t& d0, uint32_t& d1,
                                        uint32_t& d2, uint32_t& d3, uint32_t addr)
{
    asm volatile("ldmatrix.sync.aligned.m8n8.x4.shared.b16 {%0,%1,%2,%3}, [%4];"
                 : "=r"(d0), "=r"(d1), "=r"(d2), "=r"(d3) : "r"(addr));
}

// ---------------------------------------------------------------------------
// Convert kernels (one-time pre-pass)
// ---------------------------------------------------------------------------
struct CvtArgs { const float* in[3]; __half* out[3]; };

__global__ void __launch_bounds__(256)
cvt_inputs(CvtArgs a)
{
    const int z = blockIdx.z;
    const float4* in = (const float4*)a.in[z];
    __half2* out = (__half2*)a.out[z];
    const int idx = blockIdx.x * 256 + threadIdx.x;
    float4 v = in[idx];
    out[2 * idx]     = __floats2half2_rn(v.x, v.y);
    out[2 * idx + 1] = __floats2half2_rn(v.z, v.w);
}

struct TpArgs { const float* in[4]; __half* out[4]; };

__global__ void __launch_bounds__(256)
cvt_wt(TpArgs a)  // fp32 [k][n] -> fp16 [n][k]
{
    __shared__ float t[32][33];
    const float* in = a.in[blockIdx.z];
    __half* out = a.out[blockIdx.z];
    const int tx = threadIdx.x, ty = threadIdx.y;
    const int x0 = blockIdx.x * 32, y0 = blockIdx.y * 32;
#pragma unroll
    for (int j = 0; j < 32; j += 8)
        t[ty + j][tx] = in[(size_t)(y0 + ty + j) * D_MOD + x0 + tx];
    __syncthreads();
#pragma unroll
    for (int j = 0; j < 32; j += 8)
        out[(size_t)(x0 + ty + j) * D_MOD + y0 + tx] = __float2half_rn(t[tx][ty + j]);
}

// ---------------------------------------------------------------------------
// fp16 GEMM: C = alpha * A[M,K] @ Wt[Nc,K]^T, ldmatrix fragment loads.
// ---------------------------------------------------------------------------
struct HGemmArgs {
    const __half* A[3];
    const __half* Wt[3];
    void*         C[3];
    float         alpha[3];
};

#define HBK  64
#define HAS  72
#define HA_BUF (128 * HAS)
#define HGEMM_SMEM_BYTES (4 * HA_BUF * 2)

template <int NZ>
__global__ void __launch_bounds__(128)
hgemm(HGemmArgs args, int M, int Nc, int K)
{
    extern __shared__ __half hsm[];
    const uint32_t sbase = (uint32_t)__cvta_generic_to_shared(hsm);

    const int z = (NZ > 1) ? blockIdx.z : 0;
    const __half* __restrict__ A  = args.A[z];
    const __half* __restrict__ Wt = args.Wt[z];
    const float alpha = args.alpha[z];
    const bool vtr = (NZ == 3 && z == 2);

    const int tid  = threadIdx.x;
    const int lane = tid & 31;
    const int w    = tid >> 5;
    const int g    = lane >> 2;
    const int tig  = lane & 3;
    const int mbase = (w >> 1) * 64;
    const int nbase = (w & 1) * 64;
    const int bx = blockIdx.x, by = blockIdx.y;

    // ldmatrix lane selectors
    const int lr16 = lane & 15;                       // A/P row sel
    const int lc8  = (lane >> 4) << 3;                // A/P col sel
    const int bro  = (lane & 7) | ((lane >> 4) << 3); // B n-row sel
    const int bco  = lane & 8;                        // B k-col sel

    const __half* Abase = A + (size_t)(by * 128) * K;
    const __half* Wbase = Wt + (size_t)(bx * 128) * K;

    float acc[4][8][4];
#pragma unroll
    for (int mt = 0; mt < 4; ++mt)
#pragma unroll
        for (int nt = 0; nt < 8; ++nt)
#pragma unroll
            for (int i = 0; i < 4; ++i) acc[mt][nt][i] = 0.f;

    auto issue = [&](int k0, int b) {
        const uint32_t abuf = sbase + (uint32_t)(b * HA_BUF) * 2u;
        const uint32_t wbuf = sbase + (uint32_t)((2 + b) * HA_BUF) * 2u;
#pragma unroll
        for (int i = 0; i < 8; ++i) {
            const int a = tid + i * 128;
            const int r = a >> 3, c8 = a & 7;
            cp_async16(abuf + (uint32_t)(r * HAS + c8 * 8) * 2u,
                       Abase + (size_t)r * K + k0 + c8 * 8);
            cp_async16(wbuf + (uint32_t)(r * HAS + c8 * 8) * 2u,
                       Wbase + (size_t)r * K + k0 + c8 * 8);
        }
        asm volatile("cp.async.commit_group;" ::: "memory");
    };

    const int NST = K / HBK;
    issue(0, 0);
    issue(HBK, 1);

    int buf = 0;
    for (int s = 0; s < NST; ++s, buf ^= 1) {
        if (s + 1 < NST)
            asm volatile("cp.async.wait_group 1;" ::: "memory");
        else
            asm volatile("cp.async.wait_group 0;" ::: "memory");
        __syncthreads();

        const uint32_t ab = sbase + (uint32_t)(buf * HA_BUF) * 2u;
        const uint32_t wb = sbase + (uint32_t)((2 + buf) * HA_BUF) * 2u;
#pragma unroll
        for (int ks = 0; ks < 4; ++ks) {
            const int kc = ks * 16;
            uint32_t af[4][4], bf[8][2];
#pragma unroll
            for (int mt = 0; mt < 4; ++mt)
                ldsm_x4(af[mt][0], af[mt][1], af[mt][2], af[mt][3],
                        ab + (uint32_t)((mbase + mt * 16 + lr16) * HAS + kc + lc8) * 2u);
#pragma unroll
            for (int j = 0; j < 4; ++j)
                ldsm_x4(bf[2 * j][0], bf[2 * j][1], bf[2 * j + 1][0], bf[2 * j + 1][1],
                        wb + (uint32_t)((nbase + j * 16 + bro) * HAS + kc + bco) * 2u);
#pragma unroll
            for (int mt = 0; mt < 4; ++mt)
#pragma unroll
                for (int nt = 0; nt < 8; ++nt)
                    mma_f16(acc[mt][nt], af[mt][0], af[mt][1], af[mt][2], af[mt][3],
                            bf[nt][0], bf[nt][1]);
        }
        __syncthreads();
        if (s + 2 < NST) issue((s + 2) * HBK, buf);
    }

    // epilogue
#pragma unroll
    for (int mt = 0; mt < 4; ++mt) {
        const int row0 = by * 128 + mbase + mt * 16 + g;
#pragma unroll
        for (int nt = 0; nt < 8; ++nt) {
            const int col = bx * 128 + nbase + nt * 8 + tig * 2;
            const float v0 = acc[mt][nt][0] * alpha, v1 = acc[mt][nt][1] * alpha;
            const float v2 = acc[mt][nt][2] * alpha, v3 = acc[mt][nt][3] * alpha;
            if (NZ == 1) {
                float* C = (float*)args.C[0];
                *(float2*)(C + (size_t)row0 * Nc + col) = make_float2(v0, v1);
                *(float2*)(C + (size_t)(row0 + 8) * Nc + col) = make_float2(v2, v3);
            } else if (!vtr) {
                __half* C = (__half*)args.C[z];
                *(__half2*)(C + (size_t)row0 * Nc + col) = __floats2half2_rn(v0, v1);
                *(__half2*)(C + (size_t)(row0 + 8) * Nc + col) = __floats2half2_rn(v2, v3);
            } else {
                __half* C = (__half*)args.C[2];
                const int nh = col >> 6, h = col & 63;
                const int b0 = row0 >> 11, t0 = row0 & 2047;
                const size_t base0 = ((size_t)(b0 * NH + nh) * HD + h) * L_SEQ + t0;
                C[base0]             = __float2half_rn(v0);
                C[base0 + L_SEQ]     = __float2half_rn(v1);
                C[base0 + 8]         = __float2half_rn(v2);
                C[base0 + L_SEQ + 8] = __float2half_rn(v3);
            }
        }
    }
}

// ---------------------------------------------------------------------------
// fp16 flash attention, ldmatrix fragments, base-2 softmax.
// grid (L/128, B*NH), block 128 (4 warps x 32 q-rows).
// smem (halfs): Kb[2][64*72] @0, Vt[2][64*72] @9216, Pb[128*72] @18432.
// ---------------------------------------------------------------------------
#define FKH 72
#define FKB_OFF 0
#define FVB_OFF (2 * 64 * FKH)
#define FPB_OFF (FVB_OFF + 2 * 64 * FKH)
#define FLASH_SMEM_BYTES ((FPB_OFF + 128 * FKH) * 2)

__global__ void __launch_bounds__(128, 2)
flash_h(const __half* __restrict__ q, const __half* __restrict__ k,
        const __half* __restrict__ vt, __half* __restrict__ o)
{
    extern __shared__ __half hsm[];
    const uint32_t sbase = (uint32_t)__cvta_generic_to_shared(hsm);
    __half* Pb = hsm + FPB_OFF;
    const uint32_t pb_s = sbase + (uint32_t)FPB_OFF * 2u;

    const int tid  = threadIdx.x;
    const int lane = tid & 31;
    const int w    = tid >> 5;
    const int g    = lane >> 2;
    const int tig  = lane & 3;

    const int lr16 = lane & 15;
    const int lc8  = (lane >> 4) << 3;
    const int bro  = (lane & 7) | ((lane >> 4) << 3);
    const int bco  = lane & 8;

    const int bn = blockIdx.y;
    const int b  = bn >> 4;
    const int n  = bn & 15;
    const int f0 = blockIdx.x * 128;

    const __half* kbase  = k + (size_t)(b * L_SEQ) * D_MOD + n * HD;
    const __half* vtbase = vt + (size_t)(b * NH + n) * HD * L_SEQ;

    const int pr0 = 32 * w + g;
    const int pr1 = 32 * w + 16 + g;

    // ---- Q fragments from gmem (fp16, one-time; q pre-scaled by 0.125*log2e)
    uint32_t qa[2][4][4];
    {
        const __half* q00 = q + (size_t)(b * L_SEQ + f0 + pr0) * D_MOD + n * HD;
        const __half* q01 = q00 + (size_t)8 * D_MOD;
        const __half* q10 = q + (size_t)(b * L_SEQ + f0 + pr1) * D_MOD + n * HD;
        const __half* q11 = q10 + (size_t)8 * D_MOD;
#pragma unroll
        for (int ks = 0; ks < 4; ++ks) {
            const int kc = ks * 16 + tig * 2;
            qa[0][ks][0] = *(const uint32_t*)(q00 + kc);
            qa[0][ks][1] = *(const uint32_t*)(q01 + kc);
            qa[0][ks][2] = *(const uint32_t*)(q00 + kc + 8);
            qa[0][ks][3] = *(const uint32_t*)(q01 + kc + 8);
            qa[1][ks][0] = *(const uint32_t*)(q10 + kc);
            qa[1][ks][1] = *(const uint32_t*)(q11 + kc);
            qa[1][ks][2] = *(const uint32_t*)(q10 + kc + 8);
            qa[1][ks][3] = *(const uint32_t*)(q11 + kc + 8);
        }
    }

    auto issue_kv = [&](int t0, int bufi) {
        const uint32_t kb = sbase + (uint32_t)(FKB_OFF + bufi * 64 * FKH) * 2u;
        const uint32_t vb = sbase + (uint32_t)(FVB_OFF + bufi * 64 * FKH) * 2u;
#pragma unroll
        for (int i = 0; i < 4; ++i) {
            const int a = tid + i * 128;
            const int r = a >> 3, c8 = a & 7;
            cp_async16(kb + (uint32_t)(r * FKH + c8 * 8) * 2u,
                       kbase + (size_t)(t0 + r) * D_MOD + c8 * 8);
            cp_async16(vb + (uint32_t)(r * FKH + c8 * 8) * 2u,
                       vtbase + (size_t)r * L_SEQ + t0 + c8 * 8);
        }
        asm volatile("cp.async.commit_group;" ::: "memory");
    };

    float oacc[2][8][4];
#pragma unroll
    for (int mt = 0; mt < 2; ++mt)
#pragma unroll
        for (int nt = 0; nt < 8; ++nt)
#pragma unroll
            for (int i = 0; i < 4; ++i) oacc[mt][nt][i] = 0.f;
    float mrow[2][2] = {{-CUDART_INF_F, -CUDART_INF_F}, {-CUDART_INF_F, -CUDART_INF_F}};
    float lrow[2][2] = {{0.f, 0.f}, {0.f, 0.f}};

    const int NST = L_SEQ / 64;
    issue_kv(0, 0);
    issue_kv(64, 1);

    for (int s = 0; s < NST; ++s) {
        const int bufi = s & 1;
        if (s + 1 < NST)
            asm volatile("cp.async.wait_group 1;" ::: "memory");
        else
            asm volatile("cp.async.wait_group 0;" ::: "memory");
        __syncthreads();

        const uint32_t kb_s = sbase + (uint32_t)(FKB_OFF + bufi * 64 * FKH) * 2u;
        const uint32_t vb_s = sbase + (uint32_t)(FVB_OFF + bufi * 64 * FKH) * 2u;

        // ---- S = Q @ K^T (ldmatrix K)
        float sacc[2][8][4];
#pragma unroll
        for (int mt = 0; mt < 2; ++mt)
#pragma unroll
            for (int nt = 0; nt < 8; ++nt)
#pragma unroll
                for (int i = 0; i < 4; ++i) sacc[mt][nt][i] = 0.f;
#pragma unroll
        for (int ks = 0; ks < 4; ++ks) {
            const int kc = ks * 16;
            uint32_t bf[8][2];
#pragma unroll
            for (int j = 0; j < 4; ++j)
                ldsm_x4(bf[2 * j][0], bf[2 * j][1], bf[2 * j + 1][0], bf[2 * j + 1][1],
                        kb_s + (uint32_t)((j * 16 + bro) * FKH + kc + bco) * 2u);
#pragma unroll
            for (int nt = 0; nt < 8; ++nt) {
                mma_f16(sacc[0][nt], qa[0][ks][0], qa[0][ks][1], qa[0][ks][2], qa[0][ks][3],
                        bf[nt][0], bf[nt][1]);
                mma_f16(sacc[1][nt], qa[1][ks][0], qa[1][ks][1], qa[1][ks][2], qa[1][ks][3],
                        bf[nt][0], bf[nt][1]);
            }
        }

        // ---- online softmax (base-2), P -> fp16 smem
#pragma unroll
        for (int mt = 0; mt < 2; ++mt) {
            const int pr = (mt == 0) ? pr0 : pr1;
            float tm0 = -CUDART_INF_F, tm1 = -CUDART_INF_F;
#pragma unroll
            for (int nt = 0; nt < 8; ++nt) {
                tm0 = fmaxf(tm0, fmaxf(sacc[mt][nt][0], sacc[mt][nt][1]));
                tm1 = fmaxf(tm1, fmaxf(sacc[mt][nt][2], sacc[mt][nt][3]));
            }
            tm0 = fmaxf(tm0, __shfl_xor_sync(0xffffffffu, tm0, 1));
            tm0 = fmaxf(tm0, __shfl_xor_sync(0xffffffffu, tm0, 2));
            tm1 = fmaxf(tm1, __shfl_xor_sync(0xffffffffu, tm1, 1));
            tm1 = fmaxf(tm1, __shfl_xor_sync(0xffffffffu, tm1, 2));

            const float nm0 = fmaxf(mrow[mt][0], tm0);
            const float nm1 = fmaxf(mrow[mt][1], tm1);
            const float sc0 = exp2f(mrow[mt][0] - nm0);
            const float sc1 = exp2f(mrow[mt][1] - nm1);
            mrow[mt][0] = nm0; mrow[mt][1] = nm1;
            lrow[mt][0] *= sc0; lrow[mt][1] *= sc1;
#pragma unroll
            for (int nt = 0; nt < 8; ++nt) {
                oacc[mt][nt][0] *= sc0; oacc[mt][nt][1] *= sc0;
                oacc[mt][nt][2] *= sc1; oacc[mt][nt][3] *= sc1;
            }

            float rs0 = 0.f, rs1 = 0.f;
#pragma unroll
            for (int nt = 0; nt < 8; ++nt) {
                const float p0 = exp2f(sacc[mt][nt][0] - nm0);
                const float p1 = exp2f(sacc[mt][nt][1] - nm0);
                const float p2 = exp2f(sacc[mt][nt][2] - nm1);
                const float p3 = exp2f(sacc[mt][nt][3] - nm1);
                rs0 += p0 + p1;  rs1 += p2 + p3;
                const int col = nt * 8 + tig * 2;
                *(__half2*)(Pb + pr * FKH + col)       = __floats2half2_rn(p0, p1);
                *(__half2*)(Pb + (pr + 8) * FKH + col) = __floats2half2_rn(p2, p3);
            }
            rs0 += __shfl_xor_sync(0xffffffffu, rs0, 1);
            rs0 += __shfl_xor_sync(0xffffffffu, rs0, 2);
            rs1 += __shfl_xor_sync(0xffffffffu, rs1, 1);
            rs1 += __shfl_xor_sync(0xffffffffu, rs1, 2);
            lrow[mt][0] += rs0; lrow[mt][1] += rs1;
        }
        __syncwarp();

        // ---- O += P @ V (ldmatrix P and V^T)
#pragma unroll
        for (int kt = 0; kt < 4; ++kt) {
            const int kc = kt * 16;
            uint32_t pa[2][4];
            ldsm_x4(pa[0][0], pa[0][1], pa[0][2], pa[0][3],
                    pb_s + (uint32_t)((32 * w + lr16) * FKH + kc + lc8) * 2u);
            ldsm_x4(pa[1][0], pa[1][1], pa[1][2], pa[1][3],
                    pb_s + (uint32_t)((32 * w + 16 + lr16) * FKH + kc + lc8) * 2u);
            uint32_t bf[8][2];
#pragma unroll
            for (int j = 0; j < 4; ++j)
                ldsm_x4(bf[2 * j][0], bf[2 * j][1], bf[2 * j + 1][0], bf[2 * j + 1][1],
                        vb_s + (uint32_t)((j * 16 + bro) * FKH + kc + bco) * 2u);
#pragma unroll
            for (int nt = 0; nt < 8; ++nt) {
                mma_f16(oacc[0][nt], pa[0][0], pa[0][1], pa[0][2], pa[0][3],
                        bf[nt][0], bf[nt][1]);
                mma_f16(oacc[1][nt], pa[1][0], pa[1][1], pa[1][2], pa[1][3],
                        bf[nt][0], bf[nt][1]);
            }
        }
        __syncthreads();
        if (s + 2 < NST) issue_kv((s + 2) * 64, bufi);
    }

    // ---- epilogue
#pragma unroll
    for (int mt = 0; mt < 2; ++mt) {
        const int pr = (mt == 0) ? pr0 : pr1;
        const float inv0 = 1.f / lrow[mt][0];
        const float inv1 = 1.f / lrow[mt][1];
        __half* ob = o + (size_t)(b * L_SEQ + f0 + pr) * D_MOD + n * HD;
#pragma unroll
        for (int nt = 0; nt < 8; ++nt) {
            const int col = nt * 8 + tig * 2;
            *(__half2*)(ob + col) = __floats2half2_rn(oacc[mt][nt][0] * inv0,
                                                      oacc[mt][nt][1] * inv0);
            *(__half2*)(ob + (size_t)8 * D_MOD + col) = __floats2half2_rn(oacc[mt][nt][2] * inv1,
                                                                          oacc[mt][nt][3] * inv1);
        }
    }
}

// ---------------------------------------------------------------------------
// kernel_launch
// inputs: [0]=query [1]=key [2]=value [3]=Wq [4]=Wk [5]=Wv [6]=Wo
// ---------------------------------------------------------------------------
extern "C" void kernel_launch(void* const* d_in, const int* in_sizes, int n_in,
                              void* d_out, int out_size)
{
    const float* qin = (const float*)d_in[0];
    const float* kin = (const float*)d_in[1];
    const float* vin = (const float*)d_in[2];
    const float* Wq  = (const float*)d_in[3];
    const float* Wk  = (const float*)d_in[4];
    const float* Wv  = (const float*)d_in[5];
    const float* Wo  = (const float*)d_in[6];
    float* out = (float*)d_out;

    __half *inq, *ink, *inv, *wqt, *wkt, *wvt, *wot, *qh, *kh, *vt, *attnh;
    cudaGetSymbolAddress((void**)&inq,   g_inq);
    cudaGetSymbolAddress((void**)&ink,   g_ink);
    cudaGetSymbolAddress((void**)&inv,   g_inv);
    cudaGetSymbolAddress((void**)&wqt,   g_wqt);
    cudaGetSymbolAddress((void**)&wkt,   g_wkt);
    cudaGetSymbolAddress((void**)&wvt,   g_wvt);
    cudaGetSymbolAddress((void**)&wot,   g_wot);
    cudaGetSymbolAddress((void**)&qh,    g_qh);
    cudaGetSymbolAddress((void**)&kh,    g_kh);
    cudaGetSymbolAddress((void**)&vt,    g_vt);
    cudaGetSymbolAddress((void**)&attnh, g_attnh);

    cudaFuncSetAttribute(hgemm<3>, cudaFuncAttributeMaxDynamicSharedMemorySize,
                         HGEMM_SMEM_BYTES);
    cudaFuncSetAttribute(hgemm<1>, cudaFuncAttributeMaxDynamicSharedMemorySize,
                         HGEMM_SMEM_BYTES);
    cudaFuncSetAttribute(flash_h, cudaFuncAttributeMaxDynamicSharedMemorySize,
                         FLASH_SMEM_BYTES);

    // 0) convert inputs + weights (transposed) to fp16
    CvtArgs ca;
    ca.in[0] = qin; ca.in[1] = kin; ca.in[2] = vin;
    ca.out[0] = inq; ca.out[1] = ink; ca.out[2] = inv;
    cvt_inputs<<<dim3(M_ROWS * D_MOD / 4 / 256, 1, 3), 256>>>(ca);

    TpArgs ta;
    ta.in[0] = Wq; ta.in[1] = Wk; ta.in[2] = Wv; ta.in[3] = Wo;
    ta.out[0] = wqt; ta.out[1] = wkt; ta.out[2] = wvt; ta.out[3] = wot;
    cvt_wt<<<dim3(32, 32, 4), dim3(32, 8)>>>(ta);

    // 1) QKV projections (q scaled by 0.125*log2e for base-2 softmax)
    HGemmArgs qkv;
    qkv.A[0] = inq; qkv.A[1] = ink; qkv.A[2] = inv;
    qkv.Wt[0] = wqt; qkv.Wt[1] = wkt; qkv.Wt[2] = wvt;
    qkv.C[0] = qh;  qkv.C[1] = kh;  qkv.C[2] = vt;
    qkv.alpha[0] = 0.125f * 1.44269504088896341f;
    qkv.alpha[1] = 1.f;
    qkv.alpha[2] = 1.f;
    hgemm<3><<<dim3(D_MOD / 128, M_ROWS / 128, 3), 128, HGEMM_SMEM_BYTES>>>(
        qkv, M_ROWS, D_MOD, D_MOD);

    // 2) fp16 flash attention
    flash_h<<<dim3(L_SEQ / 128, B_SZ * NH), 128, FLASH_SMEM_BYTES>>>(qh, kh, vt, attnh);

    // 3) output projection (fp16 in, fp32 out)
    HGemmArgs og;
    og.A[0] = attnh; og.Wt[0] = wot; og.C[0] = out; og.alpha[0] = 1.f;
    og.A[1] = og.A[2] = nullptr; og.Wt[1] = og.Wt[2] = nullptr;
    og.C[1] = og.C[2] = nullptr; og.alpha[1] = og.alpha[2] = 0.f;
    hgemm<1><<<dim3(D_MOD / 128, M_ROWS / 128, 1), 128, HGEMM_SMEM_BYTES>>>(
        og, M_ROWS, D_MOD, D_MOD);
}